// round 1
// baseline (speedup 1.0000x reference)
#include <cuda_runtime.h>
#include <cuda_bf16.h>

#define NN 10000
#define NE 160000
#define DM 256
#define NH 8
#define HD 32
#define SCALE 0.17677669529663687f  // 1/sqrt(32)

// Scratch (device globals; no dynamic allocation allowed)
__device__ float g_Q[NN * DM];
__device__ float g_K[NN * DM];
__device__ float g_V[NN * DM];
__device__ float g_denom[NN * NH];
__device__ float g_agg[NN * DM];
__device__ float g_out[NN * DM];

// ---------------------------------------------------------------------------
// Zero the accumulators (agg + denom)
// ---------------------------------------------------------------------------
__global__ void init_kernel() {
    int total = NN * DM + NN * NH;
    for (int i = blockIdx.x * blockDim.x + threadIdx.x; i < total;
         i += gridDim.x * blockDim.x) {
        if (i < NN * DM) g_agg[i] = 0.f;
        else             g_denom[i - NN * DM] = 0.f;
    }
}

// ---------------------------------------------------------------------------
// Tiled fp32 GEMM: C = A[M,256] @ B[256,256]
// BM=64, BN=64, BK=16, 256 threads, 4x4 per-thread tile.
// blockIdx.z selects among up to 3 (W, C) pairs so QKV runs in one launch.
// ---------------------------------------------------------------------------
__global__ void gemm3_kernel(const float* __restrict__ A,
                             const float* __restrict__ W0,
                             const float* __restrict__ W1,
                             const float* __restrict__ W2,
                             float* __restrict__ C0,
                             float* __restrict__ C1,
                             float* __restrict__ C2,
                             int M) {
    const float* B = (blockIdx.z == 0) ? W0 : (blockIdx.z == 1) ? W1 : W2;
    float* C       = (blockIdx.z == 0) ? C0 : (blockIdx.z == 1) ? C1 : C2;

    __shared__ float As[16][68];  // transposed A tile, padded
    __shared__ float Bs[16][64];

    const int tx = threadIdx.x & 15;
    const int ty = threadIdx.x >> 4;
    const int m0 = blockIdx.x * 64;
    const int n0 = blockIdx.y * 64;

    float acc[4][4] = {};

    for (int k0 = 0; k0 < 256; k0 += 16) {
        // Load A tile 64x16 (float4 per thread), store transposed
        {
            int r  = threadIdx.x >> 2;
            int c4 = (threadIdx.x & 3) * 4;
            int gm = m0 + r;
            float4 a = (gm < M) ? *(const float4*)(A + gm * 256 + k0 + c4)
                                : make_float4(0.f, 0.f, 0.f, 0.f);
            As[c4 + 0][r] = a.x;
            As[c4 + 1][r] = a.y;
            As[c4 + 2][r] = a.z;
            As[c4 + 3][r] = a.w;
        }
        // Load B tile 16x64 (float4 per thread)
        {
            int r  = threadIdx.x >> 4;
            int c4 = (threadIdx.x & 15) * 4;
            *(float4*)&Bs[r][c4] = *(const float4*)(B + (k0 + r) * 256 + n0 + c4);
        }
        __syncthreads();

#pragma unroll
        for (int k = 0; k < 16; k++) {
            float4 av = *(const float4*)&As[k][ty * 4];
            float4 bv = *(const float4*)&Bs[k][tx * 4];
            float a[4] = {av.x, av.y, av.z, av.w};
            float b[4] = {bv.x, bv.y, bv.z, bv.w};
#pragma unroll
            for (int i = 0; i < 4; i++)
#pragma unroll
                for (int j = 0; j < 4; j++) acc[i][j] += a[i] * b[j];
        }
        __syncthreads();
    }

#pragma unroll
    for (int i = 0; i < 4; i++) {
        int gm = m0 + ty * 4 + i;
        if (gm < M) {
            float4 r = make_float4(acc[i][0], acc[i][1], acc[i][2], acc[i][3]);
            *(float4*)(C + gm * 256 + n0 + tx * 4) = r;
        }
    }
}

// ---------------------------------------------------------------------------
// Edge kernel: warp per edge. 8 head-dots via butterfly reduction, exp,
// atomic accumulation of denom and exp(s)*V into src buckets.
// No max-subtraction: scores are O(1) (unit-variance dot / sqrt(hd)),
// mathematically identical softmax.
// ---------------------------------------------------------------------------
__global__ void edge_kernel(const int* __restrict__ src,
                            const int* __restrict__ dst) {
    int e = blockIdx.x * (blockDim.x >> 5) + (threadIdx.x >> 5);
    if (e >= NE) return;
    int lane = threadIdx.x & 31;
    int s = src[e];
    int d = dst[e];

    const float* q = g_Q + s * DM;
    const float* k = g_K + d * DM;
    const float* v = g_V + d * DM;

    float p[NH];
#pragma unroll
    for (int h = 0; h < NH; h++)
        p[h] = q[h * HD + lane] * k[h * HD + lane];

#pragma unroll
    for (int off = 16; off; off >>= 1)
#pragma unroll
        for (int h = 0; h < NH; h++)
            p[h] += __shfl_xor_sync(0xFFFFFFFFu, p[h], off);

    float ex[NH];
#pragma unroll
    for (int h = 0; h < NH; h++) ex[h] = expf(p[h] * SCALE);

    if (lane < NH) atomicAdd(&g_denom[s * NH + lane], ex[lane]);

#pragma unroll
    for (int h = 0; h < NH; h++)
        atomicAdd(&g_agg[s * DM + h * HD + lane], ex[h] * v[h * HD + lane]);
}

// ---------------------------------------------------------------------------
// Normalize agg by denom in place (guard empty segments -> 0)
// ---------------------------------------------------------------------------
__global__ void normalize_kernel() {
    int i = blockIdx.x * blockDim.x + threadIdx.x;
    if (i >= NN * DM) return;
    int n = i >> 8;
    int h = (i >> 5) & 7;
    float den = g_denom[n * NH + h];
    g_agg[i] = (den > 0.f) ? g_agg[i] / den : 0.f;
}

// ---------------------------------------------------------------------------
// Residual + LayerNorm: out = LN(g_out + x) * gamma + beta. Block per node.
// ---------------------------------------------------------------------------
__global__ void ln_kernel(const float* __restrict__ x,
                          const float* __restrict__ gamma,
                          const float* __restrict__ beta,
                          float* __restrict__ out) {
    int n = blockIdx.x;
    int d = threadIdx.x;
    float v = g_out[n * DM + d] + x[n * DM + d];

    __shared__ float sh[8];
    float s = v;
#pragma unroll
    for (int o = 16; o; o >>= 1) s += __shfl_xor_sync(0xFFFFFFFFu, s, o);
    if ((d & 31) == 0) sh[d >> 5] = s;
    __syncthreads();
    float tot = sh[0] + sh[1] + sh[2] + sh[3] + sh[4] + sh[5] + sh[6] + sh[7];
    float mu = tot * (1.f / DM);
    float diff = v - mu;
    __syncthreads();

    float sq = diff * diff;
#pragma unroll
    for (int o = 16; o; o >>= 1) sq += __shfl_xor_sync(0xFFFFFFFFu, sq, o);
    if ((d & 31) == 0) sh[d >> 5] = sq;
    __syncthreads();
    float var = (sh[0] + sh[1] + sh[2] + sh[3] + sh[4] + sh[5] + sh[6] + sh[7])
                * (1.f / DM);

    out[n * DM + d] = diff * rsqrtf(var + 1e-5f) * gamma[d] + beta[d];
}

// ---------------------------------------------------------------------------
extern "C" void kernel_launch(void* const* d_in, const int* in_sizes, int n_in,
                              void* d_out, int out_size) {
    const float* x     = (const float*)d_in[0];
    const int*   eidx  = (const int*)d_in[1];
    const float* Wq    = (const float*)d_in[2];
    const float* Wk    = (const float*)d_in[3];
    const float* Wv    = (const float*)d_in[4];
    const float* Wo    = (const float*)d_in[5];
    const float* gamma = (const float*)d_in[6];
    const float* beta  = (const float*)d_in[7];
    float* out = (float*)d_out;

    const int* src = eidx;
    const int* dst = eidx + NE;

    float* Qp  = nullptr; cudaGetSymbolAddress((void**)&Qp,  g_Q);
    float* Kp  = nullptr; cudaGetSymbolAddress((void**)&Kp,  g_K);
    float* Vp  = nullptr; cudaGetSymbolAddress((void**)&Vp,  g_V);
    float* Ap  = nullptr; cudaGetSymbolAddress((void**)&Ap,  g_agg);
    float* Op  = nullptr; cudaGetSymbolAddress((void**)&Op,  g_out);

    // 1. zero accumulators
    init_kernel<<<512, 256>>>();

    // 2. QKV GEMMs (one launch, z selects matrix)
    dim3 gq((NN + 63) / 64, DM / 64, 3);
    gemm3_kernel<<<gq, 256>>>(x, Wq, Wk, Wv, Qp, Kp, Vp, NN);

    // 3. edge pass (warp per edge)
    edge_kernel<<<NE / 8, 256>>>(src, dst);

    // 4. normalize agg -> attn_out (in place)
    normalize_kernel<<<(NN * DM + 255) / 256, 256>>>();

    // 5. output GEMM: g_out = attn_out @ Wo
    dim3 go((NN + 63) / 64, DM / 64, 1);
    gemm3_kernel<<<go, 256>>>(Ap, Wo, Wo, Wo, Op, Op, Op, NN);

    // 6. residual + LayerNorm
    ln_kernel<<<NN, DM>>>(x, gamma, beta, out);
}

// round 2
// speedup vs baseline: 1.0297x; 1.0297x over previous
#include <cuda_runtime.h>
#include <cuda_bf16.h>

#define NN 10000
#define NE 160000
#define DM 256
#define NH 8
#define HD 32
#define SCALE 0.17677669529663687f  // 1/sqrt(32)

// Scratch (device globals; no dynamic allocation allowed)
__device__ float g_Q[NN * DM];
__device__ float g_K[NN * DM];
__device__ float g_V[NN * DM];
__device__ float g_denom[NN * NH];
__device__ float g_agg[NN * DM];
__device__ float g_out[NN * DM];

// ---- packed f32x2 helpers (Blackwell FFMA2; exact fp32 semantics) ----------
__device__ __forceinline__ unsigned long long pack2(float lo, float hi) {
    unsigned long long r;
    asm("mov.b64 %0, {%1, %2};" : "=l"(r) : "f"(lo), "f"(hi));
    return r;
}
__device__ __forceinline__ unsigned long long fma2(unsigned long long a,
                                                   unsigned long long b,
                                                   unsigned long long c) {
    unsigned long long d;
    asm("fma.rn.f32x2 %0, %1, %2, %3;" : "=l"(d) : "l"(a), "l"(b), "l"(c));
    return d;
}
__device__ __forceinline__ void unpack2(unsigned long long p, float& lo, float& hi) {
    asm("mov.b64 {%0, %1}, %2;" : "=f"(lo), "=f"(hi) : "l"(p));
}

// ---------------------------------------------------------------------------
// Zero the accumulators (agg + denom)
// ---------------------------------------------------------------------------
__global__ void init_kernel() {
    int total = NN * DM + NN * NH;
    for (int i = blockIdx.x * blockDim.x + threadIdx.x; i < total;
         i += gridDim.x * blockDim.x) {
        if (i < NN * DM) g_agg[i] = 0.f;
        else             g_denom[i - NN * DM] = 0.f;
    }
}

// ---------------------------------------------------------------------------
// Tiled fp32 GEMM (FFMA2 inner loop): C = A[M,256] @ B[256,256]
// BM=64, BN=64, BK=16, 256 threads, 4x4 per-thread tile (as 4x2 f32x2 pairs).
// blockIdx.z selects among up to 3 (W, C) pairs so QKV runs in one launch.
// If denom != nullptr, the A element at column k is scaled by
// 1/denom[row*8 + k/32] at load (fuses softmax normalization into out-GEMM).
// ---------------------------------------------------------------------------
__global__ void gemm3_kernel(const float* __restrict__ A,
                             const float* __restrict__ W0,
                             const float* __restrict__ W1,
                             const float* __restrict__ W2,
                             float* __restrict__ C0,
                             float* __restrict__ C1,
                             float* __restrict__ C2,
                             const float* __restrict__ denom,
                             int M) {
    const float* B = (blockIdx.z == 0) ? W0 : (blockIdx.z == 1) ? W1 : W2;
    float* C       = (blockIdx.z == 0) ? C0 : (blockIdx.z == 1) ? C1 : C2;

    __shared__ float As[16][68];  // transposed A tile, padded
    __shared__ float Bs[16][64];

    const int tx = threadIdx.x & 15;
    const int ty = threadIdx.x >> 4;
    const int m0 = blockIdx.x * 64;
    const int n0 = blockIdx.y * 64;

    unsigned long long acc2[4][2];
#pragma unroll
    for (int i = 0; i < 4; i++) { acc2[i][0] = 0ull; acc2[i][1] = 0ull; }

    for (int k0 = 0; k0 < 256; k0 += 16) {
        // Load A tile 64x16 (float4 per thread), store transposed
        {
            int r  = threadIdx.x >> 2;
            int c4 = (threadIdx.x & 3) * 4;
            int gm = m0 + r;
            float4 a = (gm < M) ? *(const float4*)(A + gm * 256 + k0 + c4)
                                : make_float4(0.f, 0.f, 0.f, 0.f);
            if (denom != nullptr && gm < M) {
                // head is constant across a 4-aligned chunk within a 32-wide head
                int h = (k0 + c4) >> 5;
                float den = denom[gm * NH + h];
                float inv = (den > 0.f) ? 1.f / den : 0.f;
                a.x *= inv; a.y *= inv; a.z *= inv; a.w *= inv;
            }
            As[c4 + 0][r] = a.x;
            As[c4 + 1][r] = a.y;
            As[c4 + 2][r] = a.z;
            As[c4 + 3][r] = a.w;
        }
        // Load B tile 16x64 (float4 per thread)
        {
            int r  = threadIdx.x >> 4;
            int c4 = (threadIdx.x & 15) * 4;
            *(float4*)&Bs[r][c4] = *(const float4*)(B + (k0 + r) * 256 + n0 + c4);
        }
        __syncthreads();

#pragma unroll
        for (int k = 0; k < 16; k++) {
            float4 av = *(const float4*)&As[k][ty * 4];
            float4 bv = *(const float4*)&Bs[k][tx * 4];
            unsigned long long pb0 = pack2(bv.x, bv.y);
            unsigned long long pb1 = pack2(bv.z, bv.w);
            float a[4] = {av.x, av.y, av.z, av.w};
#pragma unroll
            for (int i = 0; i < 4; i++) {
                unsigned long long pa = pack2(a[i], a[i]);
                acc2[i][0] = fma2(pa, pb0, acc2[i][0]);
                acc2[i][1] = fma2(pa, pb1, acc2[i][1]);
            }
        }
        __syncthreads();
    }

#pragma unroll
    for (int i = 0; i < 4; i++) {
        int gm = m0 + ty * 4 + i;
        if (gm < M) {
            float4 r;
            unpack2(acc2[i][0], r.x, r.y);
            unpack2(acc2[i][1], r.z, r.w);
            *(float4*)(C + gm * 256 + n0 + tx * 4) = r;
        }
    }
}

// ---------------------------------------------------------------------------
// Edge kernel: warp per edge. Lane l owns elements [8l, 8l+8) (one head per
// 4-lane group). Head dot via 2 shfls, exp, then vector (v4.f32) atomic
// reductions into the src node's agg bucket + scalar denom atomic.
// No max-subtraction needed: scores are O(1)-scaled unit-variance dots,
// softmax is shift-invariant -> mathematically identical.
// ---------------------------------------------------------------------------
__global__ void edge_kernel(const int* __restrict__ src,
                            const int* __restrict__ dst) {
    int e = blockIdx.x * (blockDim.x >> 5) + (threadIdx.x >> 5);
    if (e >= NE) return;
    int lane = threadIdx.x & 31;
    int s = src[e];
    int d = dst[e];

    const float4* q4 = (const float4*)(g_Q + s * DM);
    const float4* k4 = (const float4*)(g_K + d * DM);
    const float4* v4 = (const float4*)(g_V + d * DM);

    float4 qa = q4[2 * lane], qb = q4[2 * lane + 1];
    float4 ka = k4[2 * lane], kb = k4[2 * lane + 1];

    float p = qa.x * ka.x + qa.y * ka.y + qa.z * ka.z + qa.w * ka.w +
              qb.x * kb.x + qb.y * kb.y + qb.z * kb.z + qb.w * kb.w;
    p += __shfl_xor_sync(0xFFFFFFFFu, p, 1);
    p += __shfl_xor_sync(0xFFFFFFFFu, p, 2);

    float ex = expf(p * SCALE);

    if ((lane & 3) == 0)
        atomicAdd(&g_denom[s * NH + (lane >> 2)], ex);

    float4 va = v4[2 * lane], vb = v4[2 * lane + 1];
    float* base = g_agg + s * DM + 8 * lane;
    asm volatile("red.global.add.v4.f32 [%0], {%1, %2, %3, %4};"
                 :: "l"(base), "f"(ex * va.x), "f"(ex * va.y),
                    "f"(ex * va.z), "f"(ex * va.w) : "memory");
    asm volatile("red.global.add.v4.f32 [%0], {%1, %2, %3, %4};"
                 :: "l"(base + 4), "f"(ex * vb.x), "f"(ex * vb.y),
                    "f"(ex * vb.z), "f"(ex * vb.w) : "memory");
}

// ---------------------------------------------------------------------------
// Residual + LayerNorm: out = LN(g_out + x) * gamma + beta. Block per node.
// ---------------------------------------------------------------------------
__global__ void ln_kernel(const float* __restrict__ x,
                          const float* __restrict__ gamma,
                          const float* __restrict__ beta,
                          float* __restrict__ out) {
    int n = blockIdx.x;
    int d = threadIdx.x;
    float v = g_out[n * DM + d] + x[n * DM + d];

    __shared__ float sh[8];
    float s = v;
#pragma unroll
    for (int o = 16; o; o >>= 1) s += __shfl_xor_sync(0xFFFFFFFFu, s, o);
    if ((d & 31) == 0) sh[d >> 5] = s;
    __syncthreads();
    float tot = sh[0] + sh[1] + sh[2] + sh[3] + sh[4] + sh[5] + sh[6] + sh[7];
    float mu = tot * (1.f / DM);
    float diff = v - mu;
    __syncthreads();

    float sq = diff * diff;
#pragma unroll
    for (int o = 16; o; o >>= 1) sq += __shfl_xor_sync(0xFFFFFFFFu, sq, o);
    if ((d & 31) == 0) sh[d >> 5] = sq;
    __syncthreads();
    float var = (sh[0] + sh[1] + sh[2] + sh[3] + sh[4] + sh[5] + sh[6] + sh[7])
                * (1.f / DM);

    out[n * DM + d] = diff * rsqrtf(var + 1e-5f) * gamma[d] + beta[d];
}

// ---------------------------------------------------------------------------
extern "C" void kernel_launch(void* const* d_in, const int* in_sizes, int n_in,
                              void* d_out, int out_size) {
    const float* x     = (const float*)d_in[0];
    const int*   eidx  = (const int*)d_in[1];
    const float* Wq    = (const float*)d_in[2];
    const float* Wk    = (const float*)d_in[3];
    const float* Wv    = (const float*)d_in[4];
    const float* Wo    = (const float*)d_in[5];
    const float* gamma = (const float*)d_in[6];
    const float* beta  = (const float*)d_in[7];
    float* out = (float*)d_out;

    const int* src = eidx;
    const int* dst = eidx + NE;

    float* Qp  = nullptr; cudaGetSymbolAddress((void**)&Qp,  g_Q);
    float* Kp  = nullptr; cudaGetSymbolAddress((void**)&Kp,  g_K);
    float* Vp  = nullptr; cudaGetSymbolAddress((void**)&Vp,  g_V);
    float* Ap  = nullptr; cudaGetSymbolAddress((void**)&Ap,  g_agg);
    float* Op  = nullptr; cudaGetSymbolAddress((void**)&Op,  g_out);
    float* Dp  = nullptr; cudaGetSymbolAddress((void**)&Dp,  g_denom);

    // 1. zero accumulators
    init_kernel<<<512, 256>>>();

    // 2. QKV GEMMs (one launch, z selects matrix)
    dim3 gq((NN + 63) / 64, DM / 64, 3);
    gemm3_kernel<<<gq, 256>>>(x, Wq, Wk, Wv, Qp, Kp, Vp, nullptr, NN);

    // 3. edge pass (warp per edge)
    edge_kernel<<<NE / 8, 256>>>(src, dst);

    // 4. output GEMM with fused softmax normalization:
    //    g_out = (agg / denom) @ Wo
    dim3 go((NN + 63) / 64, DM / 64, 1);
    gemm3_kernel<<<go, 256>>>(Ap, Wo, Wo, Wo, Op, Op, Op, Dp, NN);

    // 5. residual + LayerNorm
    ln_kernel<<<NN, DM>>>(x, gamma, beta, out);
}

// round 4
// speedup vs baseline: 1.3435x; 1.3047x over previous
#include <cuda_runtime.h>
#include <cuda_bf16.h>
#include <cstdint>

#define NN 10000
#define NE 160000
#define DM 256
#define NH 8
#define HD 32
#define SCALE 0.17677669529663687f  // 1/sqrt(32)

// ---------------- device scratch (no dynamic allocation allowed) ------------
__device__ float g_Q[NN * DM];
__device__ float g_K[NN * DM];
__device__ float g_V[NN * DM];
__device__ float g_denom[NN * NH];
__device__ float g_agg[NN * DM];
__device__ float g_out[NN * DM];

// bf16 two-term split operands for tensor-core GEMMs
__device__ __nv_bfloat16 g_Ahi[NN * DM];
__device__ __nv_bfloat16 g_Alo[NN * DM];
// W matrices transposed: g_B*[z][n][k] = W_z[k][n], z in {q,k,v,o}
__device__ __nv_bfloat16 g_Bhi[4 * DM * DM];
__device__ __nv_bfloat16 g_Blo[4 * DM * DM];

__device__ __forceinline__ uint32_t smem_u32(const void* p) {
    uint32_t a;
    asm("{ .reg .u64 t; cvta.to.shared.u64 t, %1; cvt.u32.u64 %0, t; }"
        : "=r"(a) : "l"(p));
    return a;
}

// ---------------------------------------------------------------------------
// Zero the accumulators (agg + denom)
// ---------------------------------------------------------------------------
__global__ void init_kernel() {
    int total = NN * DM + NN * NH;
    for (int i = blockIdx.x * blockDim.x + threadIdx.x; i < total;
         i += gridDim.x * blockDim.x) {
        if (i < NN * DM) g_agg[i] = 0.f;
        else             g_denom[i - NN * DM] = 0.f;
    }
}

// ---------------------------------------------------------------------------
// Prep: split W matrices into hi/lo bf16, transposed to [n][k]
// ---------------------------------------------------------------------------
__global__ void prep_w_kernel(const float* __restrict__ Wq,
                              const float* __restrict__ Wk,
                              const float* __restrict__ Wv,
                              const float* __restrict__ Wo) {
    int i = blockIdx.x * blockDim.x + threadIdx.x;
    if (i >= 4 * DM * DM) return;
    int z = i >> 16;
    int r = i & 0xFFFF;
    int k = r >> 8;
    int n = r & 255;
    const float* W = (z == 0) ? Wq : (z == 1) ? Wk : (z == 2) ? Wv : Wo;
    float w = W[k * DM + n];
    __nv_bfloat16 hi = __float2bfloat16(w);
    __nv_bfloat16 lo = __float2bfloat16(w - __bfloat162float(hi));
    g_Bhi[z * DM * DM + n * DM + k] = hi;
    g_Blo[z * DM * DM + n * DM + k] = lo;
}

// ---------------------------------------------------------------------------
// Prep: split node embeddings into hi/lo bf16
// ---------------------------------------------------------------------------
__global__ void prep_a_kernel(const float* __restrict__ x) {
    int i = blockIdx.x * blockDim.x + threadIdx.x;
    if (i >= NN * DM) return;
    float v = x[i];
    __nv_bfloat16 hi = __float2bfloat16(v);
    g_Ahi[i] = hi;
    g_Alo[i] = __float2bfloat16(v - __bfloat162float(hi));
}

// ---------------------------------------------------------------------------
// Prep: (agg / denom) -> hi/lo bf16 (fuses softmax normalization)
// ---------------------------------------------------------------------------
__global__ void prep_agg_kernel() {
    int i = blockIdx.x * blockDim.x + threadIdx.x;
    if (i >= NN * DM) return;
    int n = i >> 8;
    int h = (i >> 5) & 7;
    float den = g_denom[n * NH + h];
    float v = (den > 0.f) ? g_agg[i] / den : 0.f;
    __nv_bfloat16 hi = __float2bfloat16(v);
    g_Ahi[i] = hi;
    g_Alo[i] = __float2bfloat16(v - __bfloat162float(hi));
}

// ---------------------------------------------------------------------------
// Warp-MMA GEMM (mma.sync bf16, fp32 accum): C[M,256] = A[M,256] @ W
// using B[n][k] = W[k][n] so D = A @ B^T  (row.col mma).
// Block tile 128x128, 8 warps (2m x 4n), warp tile 64x32, BK=64.
// 3 passes: Ahi*Bhi + Alo*Bhi + Ahi*Blo accumulated in fp32 registers.
// blockIdx.z selects among up to 3 weight/output pairs (QKV in one launch).
// ---------------------------------------------------------------------------
#define PAD 8
__global__ void __launch_bounds__(256, 2)
mma_gemm_kernel(const __nv_bfloat16* __restrict__ Ahi,
                const __nv_bfloat16* __restrict__ Alo,
                int zoff,
                float* __restrict__ C0, float* __restrict__ C1,
                float* __restrict__ C2, int M) {
    __shared__ __align__(16) __nv_bfloat16 sA[128][64 + PAD];
    __shared__ __align__(16) __nv_bfloat16 sB[128][64 + PAD];

    const int tid = threadIdx.x;
    const int wid = tid >> 5;
    const int lane = tid & 31;
    const int wm = wid & 1;        // 0..1  (m half: 64 rows)
    const int wn = wid >> 1;       // 0..3  (n quarter: 32 cols)
    const int z = blockIdx.z;
    float* C = (z == 0) ? C0 : (z == 1) ? C1 : C2;
    const __nv_bfloat16* Bhi = g_Bhi + (size_t)(z + zoff) * DM * DM;
    const __nv_bfloat16* Blo = g_Blo + (size_t)(z + zoff) * DM * DM;
    const int m0 = blockIdx.x * 128;
    const int n0 = blockIdx.y * 128;

    float acc[4][4][4];
#pragma unroll
    for (int i = 0; i < 4; i++)
#pragma unroll
        for (int j = 0; j < 4; j++)
#pragma unroll
            for (int r = 0; r < 4; r++) acc[i][j][r] = 0.f;

    // ldmatrix source addresses (computed once)
    // A (x4, 16x16 tile): lane -> row = lane%16, col-half = lane/16
    const int a_r = lane & 15;
    const int a_c = (lane >> 4) << 3;
    // B (x2, 8n x 16k tile): lanes 0-7 -> k 0..7, lanes 8-15 -> k 8..15
    const int b_r = lane & 7;
    const int b_c = ((lane >> 3) & 1) << 3;

#pragma unroll 1
    for (int pass = 0; pass < 3; pass++) {
        const __nv_bfloat16* Ap = (pass == 1) ? Alo : Ahi;
        const __nv_bfloat16* Bp = (pass == 2) ? Blo : Bhi;

#pragma unroll 1
        for (int kc = 0; kc < 4; kc++) {
            const int k0 = kc * 64;
            // ---- fill smem: 128 rows x 64 bf16 each, uint4 = 8 bf16 ----
#pragma unroll
            for (int it = 0; it < 4; it++) {
                int idx = it * 256 + tid;
                int r = idx >> 3;
                int c8 = (idx & 7) << 3;
                int gm = m0 + r;
                uint4 va = (gm < M)
                    ? *(const uint4*)(Ap + (size_t)gm * DM + k0 + c8)
                    : make_uint4(0, 0, 0, 0);
                *(uint4*)(&sA[r][c8]) = va;
                uint4 vb = *(const uint4*)(Bp + (size_t)(n0 + r) * DM + k0 + c8);
                *(uint4*)(&sB[r][c8]) = vb;
            }
            __syncthreads();

            // ---- compute: 4 k16 steps ----
#pragma unroll
            for (int ks = 0; ks < 4; ks++) {
                const int koff = ks * 16;
                uint32_t a[4][4];
#pragma unroll
                for (int i = 0; i < 4; i++) {
                    uint32_t addr = smem_u32(&sA[wm * 64 + i * 16 + a_r][koff + a_c]);
                    asm volatile(
                        "ldmatrix.sync.aligned.m8n8.x4.shared.b16 {%0,%1,%2,%3}, [%4];"
                        : "=r"(a[i][0]), "=r"(a[i][1]), "=r"(a[i][2]), "=r"(a[i][3])
                        : "r"(addr));
                }
                uint32_t b[4][2];
#pragma unroll
                for (int j = 0; j < 4; j++) {
                    uint32_t addr = smem_u32(&sB[wn * 32 + j * 8 + b_r][koff + b_c]);
                    asm volatile(
                        "ldmatrix.sync.aligned.m8n8.x2.shared.b16 {%0,%1}, [%2];"
                        : "=r"(b[j][0]), "=r"(b[j][1])
                        : "r"(addr));
                }
#pragma unroll
                for (int i = 0; i < 4; i++)
#pragma unroll
                    for (int j = 0; j < 4; j++) {
                        asm volatile(
                            "mma.sync.aligned.m16n8k16.row.col.f32.bf16.bf16.f32 "
                            "{%0,%1,%2,%3}, {%4,%5,%6,%7}, {%8,%9}, {%0,%1,%2,%3};"
                            : "+f"(acc[i][j][0]), "+f"(acc[i][j][1]),
                              "+f"(acc[i][j][2]), "+f"(acc[i][j][3])
                            : "r"(a[i][0]), "r"(a[i][1]), "r"(a[i][2]), "r"(a[i][3]),
                              "r"(b[j][0]), "r"(b[j][1]));
                    }
            }
            __syncthreads();
        }
    }

    // ---- epilogue: D fragment lane mapping: rows lane/4 (+8), cols (lane%4)*2
    const int er = lane >> 2;
    const int ec = (lane & 3) << 1;
#pragma unroll
    for (int i = 0; i < 4; i++) {
        int gm0 = m0 + wm * 64 + i * 16 + er;
#pragma unroll
        for (int j = 0; j < 4; j++) {
            int gc = n0 + wn * 32 + j * 8 + ec;
            if (gm0 < M)
                *(float2*)(C + (size_t)gm0 * DM + gc) =
                    make_float2(acc[i][j][0], acc[i][j][1]);
            if (gm0 + 8 < M)
                *(float2*)(C + (size_t)(gm0 + 8) * DM + gc) =
                    make_float2(acc[i][j][2], acc[i][j][3]);
        }
    }
}

// ---------------------------------------------------------------------------
// Edge kernel: warp per edge. Lane l owns elements [8l, 8l+8) (one head per
// 4-lane group). Head dot via 2 shfls, exp, vector red atomics into src.
// No max-subtraction needed: softmax is shift-invariant and scores are O(1).
// ---------------------------------------------------------------------------
__global__ void edge_kernel(const int* __restrict__ src,
                            const int* __restrict__ dst) {
    int e = blockIdx.x * (blockDim.x >> 5) + (threadIdx.x >> 5);
    if (e >= NE) return;
    int lane = threadIdx.x & 31;
    int s = src[e];
    int d = dst[e];

    const float4* q4 = (const float4*)(g_Q + s * DM);
    const float4* k4 = (const float4*)(g_K + d * DM);
    const float4* v4 = (const float4*)(g_V + d * DM);

    float4 qa = q4[2 * lane], qb = q4[2 * lane + 1];
    float4 ka = k4[2 * lane], kb = k4[2 * lane + 1];

    float p = qa.x * ka.x + qa.y * ka.y + qa.z * ka.z + qa.w * ka.w +
              qb.x * kb.x + qb.y * kb.y + qb.z * kb.z + qb.w * kb.w;
    p += __shfl_xor_sync(0xFFFFFFFFu, p, 1);
    p += __shfl_xor_sync(0xFFFFFFFFu, p, 2);

    float ex = expf(p * SCALE);

    if ((lane & 3) == 0)
        atomicAdd(&g_denom[s * NH + (lane >> 2)], ex);

    float4 va = v4[2 * lane], vb = v4[2 * lane + 1];
    float* base = g_agg + s * DM + 8 * lane;
    asm volatile("red.global.add.v4.f32 [%0], {%1, %2, %3, %4};"
                 :: "l"(base), "f"(ex * va.x), "f"(ex * va.y),
                    "f"(ex * va.z), "f"(ex * va.w) : "memory");
    asm volatile("red.global.add.v4.f32 [%0], {%1, %2, %3, %4};"
                 :: "l"(base + 4), "f"(ex * vb.x), "f"(ex * vb.y),
                    "f"(ex * vb.z), "f"(ex * vb.w) : "memory");
}

// ---------------------------------------------------------------------------
// Residual + LayerNorm: out = LN(g_out + x) * gamma + beta. Block per node.
// ---------------------------------------------------------------------------
__global__ void ln_kernel(const float* __restrict__ x,
                          const float* __restrict__ gamma,
                          const float* __restrict__ beta,
                          float* __restrict__ out) {
    int n = blockIdx.x;
    int d = threadIdx.x;
    float v = g_out[n * DM + d] + x[n * DM + d];

    __shared__ float sh[8];
    float s = v;
#pragma unroll
    for (int o = 16; o; o >>= 1) s += __shfl_xor_sync(0xFFFFFFFFu, s, o);
    if ((d & 31) == 0) sh[d >> 5] = s;
    __syncthreads();
    float tot = sh[0] + sh[1] + sh[2] + sh[3] + sh[4] + sh[5] + sh[6] + sh[7];
    float mu = tot * (1.f / DM);
    float diff = v - mu;
    __syncthreads();

    float sq = diff * diff;
#pragma unroll
    for (int o = 16; o; o >>= 1) sq += __shfl_xor_sync(0xFFFFFFFFu, sq, o);
    if ((d & 31) == 0) sh[d >> 5] = sq;
    __syncthreads();
    float var = (sh[0] + sh[1] + sh[2] + sh[3] + sh[4] + sh[5] + sh[6] + sh[7])
                * (1.f / DM);

    out[n * DM + d] = diff * rsqrtf(var + 1e-5f) * gamma[d] + beta[d];
}

// ---------------------------------------------------------------------------
extern "C" void kernel_launch(void* const* d_in, const int* in_sizes, int n_in,
                              void* d_out, int out_size) {
    const float* x     = (const float*)d_in[0];
    const int*   eidx  = (const int*)d_in[1];
    const float* Wq    = (const float*)d_in[2];
    const float* Wk    = (const float*)d_in[3];
    const float* Wv    = (const float*)d_in[4];
    const float* Wo    = (const float*)d_in[5];
    const float* gamma = (const float*)d_in[6];
    const float* beta  = (const float*)d_in[7];
    float* out = (float*)d_out;

    const int* src = eidx;
    const int* dst = eidx + NE;

    float* Qp = nullptr; cudaGetSymbolAddress((void**)&Qp, g_Q);
    float* Kp = nullptr; cudaGetSymbolAddress((void**)&Kp, g_K);
    float* Vp = nullptr; cudaGetSymbolAddress((void**)&Vp, g_V);
    float* Op = nullptr; cudaGetSymbolAddress((void**)&Op, g_out);
    __nv_bfloat16* Ahip = nullptr; cudaGetSymbolAddress((void**)&Ahip, g_Ahi);
    __nv_bfloat16* Alop = nullptr; cudaGetSymbolAddress((void**)&Alop, g_Alo);

    // 1. zero accumulators
    init_kernel<<<512, 256>>>();

    // 2. operand prep: W hi/lo transposed, x hi/lo
    prep_w_kernel<<<(4 * DM * DM + 255) / 256, 256>>>(Wq, Wk, Wv, Wo);
    prep_a_kernel<<<(NN * DM + 255) / 256, 256>>>(x);

    // 3. QKV tensor-core GEMMs (z selects matrix)
    dim3 gq((NN + 127) / 128, DM / 128, 3);
    mma_gemm_kernel<<<gq, 256>>>(Ahip, Alop, 0, Qp, Kp, Vp, NN);

    // 4. edge pass (warp per edge)
    edge_kernel<<<NE / 8, 256>>>(src, dst);

    // 5. normalize + split agg for output GEMM
    prep_agg_kernel<<<(NN * DM + 255) / 256, 256>>>();

    // 6. output GEMM: g_out = (agg/denom) @ Wo
    dim3 go((NN + 127) / 128, DM / 128, 1);
    mma_gemm_kernel<<<go, 256>>>(Ahip, Alop, 3, Op, Op, Op, NN);

    // 7. residual + LayerNorm
    ln_kernel<<<NN, DM>>>(x, gamma, beta, out);
}

// round 5
// speedup vs baseline: 1.6232x; 1.2082x over previous
#include <cuda_runtime.h>
#include <cuda_bf16.h>
#include <cstdint>

#define NN 10000
#define NE 160000
#define DM 256
#define NH 8
#define HD 32
#define SCALE 0.17677669529663687f  // 1/sqrt(32)

// ---------------- device scratch (no dynamic allocation allowed) ------------
__device__ float g_Q[NN * DM];
__device__ float g_K[NN * DM];
__device__ float g_V[NN * DM];
__device__ float g_out[NN * DM];

// bf16 two-term split operands for tensor-core GEMMs
__device__ __nv_bfloat16 g_Ahi[NN * DM];
__device__ __nv_bfloat16 g_Alo[NN * DM];
// W matrices transposed: g_B*[z][n][k] = W_z[k][n], z in {q,k,v,o}
__device__ __nv_bfloat16 g_Bhi[4 * DM * DM];
__device__ __nv_bfloat16 g_Blo[4 * DM * DM];

// CSR over src
__device__ int g_cnt[NN];
__device__ int g_off[NN + 1];
__device__ int g_cur[NN];
__device__ int g_edst[NE];

__device__ __forceinline__ uint32_t smem_u32(const void* p) {
    uint32_t a;
    asm("{ .reg .u64 t; cvta.to.shared.u64 t, %1; cvt.u32.u64 %0, t; }"
        : "=r"(a) : "l"(p));
    return a;
}

// ---------------------------------------------------------------------------
// CSR build: zero counts, histogram, scan, scatter
// ---------------------------------------------------------------------------
__global__ void zero_cnt_kernel() {
    int i = blockIdx.x * blockDim.x + threadIdx.x;
    if (i < NN) g_cnt[i] = 0;
}

__global__ void hist_kernel(const int* __restrict__ src) {
    int e = blockIdx.x * blockDim.x + threadIdx.x;
    if (e < NE) atomicAdd(&g_cnt[src[e]], 1);
}

// One-CTA scan: 1024 threads, each owns 10 consecutive counts.
__global__ void scan_kernel() {
    __shared__ int spart[1024];
    int t = threadIdx.x;
    int base = t * 10;
    int local[10];
    int s = 0;
#pragma unroll
    for (int j = 0; j < 10; j++) {
        int idx = base + j;
        int c = (idx < NN) ? g_cnt[idx] : 0;
        local[j] = s;
        s += c;
    }
    spart[t] = s;
    __syncthreads();
#pragma unroll
    for (int off = 1; off < 1024; off <<= 1) {
        int v = (t >= off) ? spart[t - off] : 0;
        __syncthreads();
        spart[t] += v;
        __syncthreads();
    }
    int tpre = (t > 0) ? spart[t - 1] : 0;
#pragma unroll
    for (int j = 0; j < 10; j++) {
        int idx = base + j;
        if (idx < NN) {
            int o = tpre + local[j];
            g_off[idx] = o;
            g_cur[idx] = o;
        }
    }
    if (t == 1023) g_off[NN] = spart[1023];
}

__global__ void scatter_kernel(const int* __restrict__ src,
                               const int* __restrict__ dst) {
    int e = blockIdx.x * blockDim.x + threadIdx.x;
    if (e >= NE) return;
    int pos = atomicAdd(&g_cur[src[e]], 1);
    g_edst[pos] = dst[e];
}

// ---------------------------------------------------------------------------
// Prep: split W matrices into hi/lo bf16, transposed to [n][k]
// ---------------------------------------------------------------------------
__global__ void prep_w_kernel(const float* __restrict__ Wq,
                              const float* __restrict__ Wk,
                              const float* __restrict__ Wv,
                              const float* __restrict__ Wo) {
    int i = blockIdx.x * blockDim.x + threadIdx.x;
    if (i >= 4 * DM * DM) return;
    int z = i >> 16;
    int r = i & 0xFFFF;
    int k = r >> 8;
    int n = r & 255;
    const float* W = (z == 0) ? Wq : (z == 1) ? Wk : (z == 2) ? Wv : Wo;
    float w = W[k * DM + n];
    __nv_bfloat16 hi = __float2bfloat16(w);
    __nv_bfloat16 lo = __float2bfloat16(w - __bfloat162float(hi));
    g_Bhi[z * DM * DM + n * DM + k] = hi;
    g_Blo[z * DM * DM + n * DM + k] = lo;
}

// ---------------------------------------------------------------------------
// Prep: split node embeddings into hi/lo bf16
// ---------------------------------------------------------------------------
__global__ void prep_a_kernel(const float* __restrict__ x) {
    int i = blockIdx.x * blockDim.x + threadIdx.x;
    if (i >= NN * DM) return;
    float v = x[i];
    __nv_bfloat16 hi = __float2bfloat16(v);
    g_Ahi[i] = hi;
    g_Alo[i] = __float2bfloat16(v - __bfloat162float(hi));
}

// ---------------------------------------------------------------------------
// Warp-MMA GEMM (mma.sync bf16, fp32 accum): C[M,256] = A[M,256] @ W
// using B[n][k] = W[k][n] so D = A @ B^T  (row.col mma).
// Block tile 128x128, 8 warps (2m x 4n), warp tile 64x32, BK=64.
// A/B hi+lo chunks all resident in smem: ONE fill per k-chunk; fragments
// loaded once (hi+lo), 3 mma passes (hh, lh, hl) from registers.
// ---------------------------------------------------------------------------
#define SSTR 72   // smem row stride (bf16 elems), 144B -> conflict-free ldmatrix
#define SM_CHUNK (128 * SSTR)
#define GEMM_SMEM (4 * SM_CHUNK * 2)  // 73728 bytes

__global__ void __launch_bounds__(256, 2)
mma_gemm_kernel(const __nv_bfloat16* __restrict__ Ahi,
                const __nv_bfloat16* __restrict__ Alo,
                int zoff,
                float* __restrict__ C0, float* __restrict__ C1,
                float* __restrict__ C2, int M) {
    extern __shared__ __nv_bfloat16 sm[];
    __nv_bfloat16* sAhi = sm;
    __nv_bfloat16* sAlo = sm + SM_CHUNK;
    __nv_bfloat16* sBhi = sm + 2 * SM_CHUNK;
    __nv_bfloat16* sBlo = sm + 3 * SM_CHUNK;

    const int tid = threadIdx.x;
    const int wid = tid >> 5;
    const int lane = tid & 31;
    const int wm = wid & 1;        // m half (64 rows)
    const int wn = wid >> 1;       // n quarter (32 cols)
    const int z = blockIdx.z;
    float* C = (z == 0) ? C0 : (z == 1) ? C1 : C2;
    const __nv_bfloat16* Bhi = g_Bhi + (size_t)(z + zoff) * DM * DM;
    const __nv_bfloat16* Blo = g_Blo + (size_t)(z + zoff) * DM * DM;
    const int m0 = blockIdx.x * 128;
    const int n0 = blockIdx.y * 128;

    float acc[4][4][4];
#pragma unroll
    for (int i = 0; i < 4; i++)
#pragma unroll
        for (int j = 0; j < 4; j++)
#pragma unroll
            for (int r = 0; r < 4; r++) acc[i][j][r] = 0.f;

    // ldmatrix lane address components
    const int a_r = lane & 15;
    const int a_c = (lane >> 4) << 3;
    const int b_r = lane & 7;
    const int b_c = ((lane >> 3) & 1) << 3;

#pragma unroll 1
    for (int kc = 0; kc < 4; kc++) {
        const int k0 = kc * 64;
        // ---- fill all four chunks: 128 rows x 64 bf16 each ----
#pragma unroll
        for (int it = 0; it < 4; it++) {
            int idx = it * 256 + tid;
            int r = idx >> 3;
            int c8 = (idx & 7) << 3;
            int gm = m0 + r;
            uint4 vah, val;
            if (gm < M) {
                vah = *(const uint4*)(Ahi + (size_t)gm * DM + k0 + c8);
                val = *(const uint4*)(Alo + (size_t)gm * DM + k0 + c8);
            } else {
                vah = make_uint4(0, 0, 0, 0);
                val = vah;
            }
            *(uint4*)(&sAhi[r * SSTR + c8]) = vah;
            *(uint4*)(&sAlo[r * SSTR + c8]) = val;
            uint4 vbh = *(const uint4*)(Bhi + (size_t)(n0 + r) * DM + k0 + c8);
            uint4 vbl = *(const uint4*)(Blo + (size_t)(n0 + r) * DM + k0 + c8);
            *(uint4*)(&sBhi[r * SSTR + c8]) = vbh;
            *(uint4*)(&sBlo[r * SSTR + c8]) = vbl;
        }
        __syncthreads();

        // ---- compute: 4 k16 steps ----
#pragma unroll
        for (int ks = 0; ks < 4; ks++) {
            const int koff = ks * 16;
            uint32_t ah[4][4], al[4][4];
#pragma unroll
            for (int i = 0; i < 4; i++) {
                int row = wm * 64 + i * 16 + a_r;
                uint32_t addr = smem_u32(&sAhi[row * SSTR + koff + a_c]);
                asm volatile(
                    "ldmatrix.sync.aligned.m8n8.x4.shared.b16 {%0,%1,%2,%3}, [%4];"
                    : "=r"(ah[i][0]), "=r"(ah[i][1]), "=r"(ah[i][2]), "=r"(ah[i][3])
                    : "r"(addr));
                uint32_t addr2 = smem_u32(&sAlo[row * SSTR + koff + a_c]);
                asm volatile(
                    "ldmatrix.sync.aligned.m8n8.x4.shared.b16 {%0,%1,%2,%3}, [%4];"
                    : "=r"(al[i][0]), "=r"(al[i][1]), "=r"(al[i][2]), "=r"(al[i][3])
                    : "r"(addr2));
            }
            uint32_t b[4][2];
            // pass hh + lh (share b_hi)
#pragma unroll
            for (int j = 0; j < 4; j++) {
                int row = wn * 32 + j * 8 + b_r;
                uint32_t addr = smem_u32(&sBhi[row * SSTR + koff + b_c]);
                asm volatile(
                    "ldmatrix.sync.aligned.m8n8.x2.shared.b16 {%0,%1}, [%2];"
                    : "=r"(b[j][0]), "=r"(b[j][1]) : "r"(addr));
            }
#pragma unroll
            for (int i = 0; i < 4; i++)
#pragma unroll
                for (int j = 0; j < 4; j++)
                    asm volatile(
                        "mma.sync.aligned.m16n8k16.row.col.f32.bf16.bf16.f32 "
                        "{%0,%1,%2,%3}, {%4,%5,%6,%7}, {%8,%9}, {%0,%1,%2,%3};"
                        : "+f"(acc[i][j][0]), "+f"(acc[i][j][1]),
                          "+f"(acc[i][j][2]), "+f"(acc[i][j][3])
                        : "r"(ah[i][0]), "r"(ah[i][1]), "r"(ah[i][2]), "r"(ah[i][3]),
                          "r"(b[j][0]), "r"(b[j][1]));
#pragma unroll
            for (int i = 0; i < 4; i++)
#pragma unroll
                for (int j = 0; j < 4; j++)
                    asm volatile(
                        "mma.sync.aligned.m16n8k16.row.col.f32.bf16.bf16.f32 "
                        "{%0,%1,%2,%3}, {%4,%5,%6,%7}, {%8,%9}, {%0,%1,%2,%3};"
                        : "+f"(acc[i][j][0]), "+f"(acc[i][j][1]),
                          "+f"(acc[i][j][2]), "+f"(acc[i][j][3])
                        : "r"(al[i][0]), "r"(al[i][1]), "r"(al[i][2]), "r"(al[i][3]),
                          "r"(b[j][0]), "r"(b[j][1]));
            // pass hl (b_lo)
#pragma unroll
            for (int j = 0; j < 4; j++) {
                int row = wn * 32 + j * 8 + b_r;
                uint32_t addr = smem_u32(&sBlo[row * SSTR + koff + b_c]);
                asm volatile(
                    "ldmatrix.sync.aligned.m8n8.x2.shared.b16 {%0,%1}, [%2];"
                    : "=r"(b[j][0]), "=r"(b[j][1]) : "r"(addr));
            }
#pragma unroll
            for (int i = 0; i < 4; i++)
#pragma unroll
                for (int j = 0; j < 4; j++)
                    asm volatile(
                        "mma.sync.aligned.m16n8k16.row.col.f32.bf16.bf16.f32 "
                        "{%0,%1,%2,%3}, {%4,%5,%6,%7}, {%8,%9}, {%0,%1,%2,%3};"
                        : "+f"(acc[i][j][0]), "+f"(acc[i][j][1]),
                          "+f"(acc[i][j][2]), "+f"(acc[i][j][3])
                        : "r"(ah[i][0]), "r"(ah[i][1]), "r"(ah[i][2]), "r"(ah[i][3]),
                          "r"(b[j][0]), "r"(b[j][1]));
        }
        __syncthreads();
    }

    // ---- epilogue ----
    const int er = lane >> 2;
    const int ec = (lane & 3) << 1;
#pragma unroll
    for (int i = 0; i < 4; i++) {
        int gm0 = m0 + wm * 64 + i * 16 + er;
#pragma unroll
        for (int j = 0; j < 4; j++) {
            int gc = n0 + wn * 32 + j * 8 + ec;
            if (gm0 < M)
                *(float2*)(C + (size_t)gm0 * DM + gc) =
                    make_float2(acc[i][j][0], acc[i][j][1]);
            if (gm0 + 8 < M)
                *(float2*)(C + (size_t)(gm0 + 8) * DM + gc) =
                    make_float2(acc[i][j][2], acc[i][j][3]);
        }
    }
}

// ---------------------------------------------------------------------------
// Node aggregation: warp per node. Q row in registers, stream neighbor K/V
// rows, softmax accumulate in registers, write normalized result directly as
// hi/lo bf16 split (input to the output GEMM). No atomics.
// Lane l owns elements [8l, 8l+8); head = lane/4; head dot via 2 shfls.
// ---------------------------------------------------------------------------
__global__ void node_agg_kernel() {
    int n = blockIdx.x * (blockDim.x >> 5) + (threadIdx.x >> 5);
    if (n >= NN) return;
    int lane = threadIdx.x & 31;

    const float4* q4 = (const float4*)(g_Q + (size_t)n * DM);
    float4 qa = q4[2 * lane], qb = q4[2 * lane + 1];

    int beg = g_off[n];
    int end = g_off[n + 1];

    float acc[8] = {0.f, 0.f, 0.f, 0.f, 0.f, 0.f, 0.f, 0.f};
    float den = 0.f;

#pragma unroll 2
    for (int i = beg; i < end; i++) {
        int d = g_edst[i];
        const float4* k4 = (const float4*)(g_K + (size_t)d * DM);
        const float4* v4 = (const float4*)(g_V + (size_t)d * DM);
        float4 ka = k4[2 * lane], kb = k4[2 * lane + 1];
        float4 va = v4[2 * lane], vb = v4[2 * lane + 1];

        float p = qa.x * ka.x + qa.y * ka.y + qa.z * ka.z + qa.w * ka.w +
                  qb.x * kb.x + qb.y * kb.y + qb.z * kb.z + qb.w * kb.w;
        p += __shfl_xor_sync(0xFFFFFFFFu, p, 1);
        p += __shfl_xor_sync(0xFFFFFFFFu, p, 2);

        float ex = expf(p * SCALE);
        den += ex;
        acc[0] += ex * va.x; acc[1] += ex * va.y;
        acc[2] += ex * va.z; acc[3] += ex * va.w;
        acc[4] += ex * vb.x; acc[5] += ex * vb.y;
        acc[6] += ex * vb.z; acc[7] += ex * vb.w;
    }

    float inv = (den > 0.f) ? 1.f / den : 0.f;
    __nv_bfloat16 hi8[8], lo8[8];
#pragma unroll
    for (int j = 0; j < 8; j++) {
        float v = acc[j] * inv;
        __nv_bfloat16 hi = __float2bfloat16(v);
        hi8[j] = hi;
        lo8[j] = __float2bfloat16(v - __bfloat162float(hi));
    }
    size_t base = (size_t)n * DM + 8 * lane;
    *(uint4*)(g_Ahi + base) = *(const uint4*)hi8;
    *(uint4*)(g_Alo + base) = *(const uint4*)lo8;
}

// ---------------------------------------------------------------------------
// Residual + LayerNorm: out = LN(g_out + x) * gamma + beta. Block per node.
// ---------------------------------------------------------------------------
__global__ void ln_kernel(const float* __restrict__ x,
                          const float* __restrict__ gamma,
                          const float* __restrict__ beta,
                          float* __restrict__ out) {
    int n = blockIdx.x;
    int d = threadIdx.x;
    float v = g_out[n * DM + d] + x[n * DM + d];

    __shared__ float sh[8];
    float s = v;
#pragma unroll
    for (int o = 16; o; o >>= 1) s += __shfl_xor_sync(0xFFFFFFFFu, s, o);
    if ((d & 31) == 0) sh[d >> 5] = s;
    __syncthreads();
    float tot = sh[0] + sh[1] + sh[2] + sh[3] + sh[4] + sh[5] + sh[6] + sh[7];
    float mu = tot * (1.f / DM);
    float diff = v - mu;
    __syncthreads();

    float sq = diff * diff;
#pragma unroll
    for (int o = 16; o; o >>= 1) sq += __shfl_xor_sync(0xFFFFFFFFu, sq, o);
    if ((d & 31) == 0) sh[d >> 5] = sq;
    __syncthreads();
    float var = (sh[0] + sh[1] + sh[2] + sh[3] + sh[4] + sh[5] + sh[6] + sh[7])
                * (1.f / DM);

    out[n * DM + d] = diff * rsqrtf(var + 1e-5f) * gamma[d] + beta[d];
}

// ---------------------------------------------------------------------------
extern "C" void kernel_launch(void* const* d_in, const int* in_sizes, int n_in,
                              void* d_out, int out_size) {
    const float* x     = (const float*)d_in[0];
    const int*   eidx  = (const int*)d_in[1];
    const float* Wq    = (const float*)d_in[2];
    const float* Wk    = (const float*)d_in[3];
    const float* Wv    = (const float*)d_in[4];
    const float* Wo    = (const float*)d_in[5];
    const float* gamma = (const float*)d_in[6];
    const float* beta  = (const float*)d_in[7];
    float* out = (float*)d_out;

    const int* src = eidx;
    const int* dst = eidx + NE;

    float* Qp = nullptr; cudaGetSymbolAddress((void**)&Qp, g_Q);
    float* Kp = nullptr; cudaGetSymbolAddress((void**)&Kp, g_K);
    float* Vp = nullptr; cudaGetSymbolAddress((void**)&Vp, g_V);
    float* Op = nullptr; cudaGetSymbolAddress((void**)&Op, g_out);
    __nv_bfloat16* Ahip = nullptr; cudaGetSymbolAddress((void**)&Ahip, g_Ahi);
    __nv_bfloat16* Alop = nullptr; cudaGetSymbolAddress((void**)&Alop, g_Alo);

    cudaFuncSetAttribute(mma_gemm_kernel,
                         cudaFuncAttributeMaxDynamicSharedMemorySize, GEMM_SMEM);

    // CSR build (depends only on edge_index)
    zero_cnt_kernel<<<(NN + 255) / 256, 256>>>();
    hist_kernel<<<(NE + 255) / 256, 256>>>(src);
    scan_kernel<<<1, 1024>>>();
    scatter_kernel<<<(NE + 255) / 256, 256>>>(src, dst);

    // operand prep: W hi/lo transposed, x hi/lo
    prep_w_kernel<<<(4 * DM * DM + 255) / 256, 256>>>(Wq, Wk, Wv, Wo);
    prep_a_kernel<<<(NN * DM + 255) / 256, 256>>>(x);

    // QKV tensor-core GEMMs (z selects matrix)
    dim3 gq((NN + 127) / 128, DM / 128, 3);
    mma_gemm_kernel<<<gq, 256, GEMM_SMEM>>>(Ahip, Alop, 0, Qp, Kp, Vp, NN);

    // per-node softmax aggregation (writes Ahi/Alo directly)
    node_agg_kernel<<<(NN * 32 + 255) / 256, 256>>>();

    // output GEMM: g_out = (agg/denom) @ Wo
    dim3 go((NN + 127) / 128, DM / 128, 1);
    mma_gemm_kernel<<<go, 256, GEMM_SMEM>>>(Ahip, Alop, 3, Op, Op, Op, NN);

    // residual + LayerNorm
    ln_kernel<<<NN, DM>>>(x, gamma, beta, out);
}

// round 6
// speedup vs baseline: 1.6409x; 1.0109x over previous
#include <cuda_runtime.h>
#include <cuda_bf16.h>
#include <cstdint>

#define NN 10000
#define NE 160000
#define DM 256
#define NH 8
#define HD 32
#define SCALE 0.17677669529663687f  // 1/sqrt(32)

// ---------------- device scratch (no dynamic allocation allowed) ------------
__device__ float g_Q[NN * DM];
__device__ float g_K[NN * DM];
__device__ float g_V[NN * DM];
__device__ float g_out[NN * DM];

// bf16 two-term split operands for tensor-core GEMMs
__device__ __nv_bfloat16 g_Ahi[NN * DM];
__device__ __nv_bfloat16 g_Alo[NN * DM];
// W matrices transposed: g_B*[z][n][k] = W_z[k][n], z in {q,k,v,o}
__device__ __nv_bfloat16 g_Bhi[4 * DM * DM];
__device__ __nv_bfloat16 g_Blo[4 * DM * DM];

// CSR over src
__device__ int g_cnt[NN];
__device__ int g_off[NN + 1];
__device__ int g_cur[NN];
__device__ int g_edst[NE];

__device__ __forceinline__ uint32_t smem_u32(const void* p) {
    uint32_t a;
    asm("{ .reg .u64 t; cvta.to.shared.u64 t, %1; cvt.u32.u64 %0, t; }"
        : "=r"(a) : "l"(p));
    return a;
}

__device__ __forceinline__ void cp_async16(uint32_t saddr, const void* gaddr,
                                           uint32_t src_sz) {
    asm volatile("cp.async.cg.shared.global [%0], [%1], 16, %2;"
                 :: "r"(saddr), "l"(gaddr), "r"(src_sz));
}
__device__ __forceinline__ void cp_commit() {
    asm volatile("cp.async.commit_group;" ::: "memory");
}
template <int N>
__device__ __forceinline__ void cp_wait() {
    asm volatile("cp.async.wait_group %0;" :: "n"(N) : "memory");
}

// ---------------------------------------------------------------------------
// CSR build: histogram, scan, scatter
// ---------------------------------------------------------------------------
__global__ void hist_kernel(const int* __restrict__ src) {
    int e = blockIdx.x * blockDim.x + threadIdx.x;
    if (e < NE) atomicAdd(&g_cnt[src[e]], 1);
}

// One-CTA scan: 1024 threads, each owns 10 consecutive counts.
__global__ void scan_kernel() {
    __shared__ int spart[1024];
    int t = threadIdx.x;
    int base = t * 10;
    int local[10];
    int s = 0;
#pragma unroll
    for (int j = 0; j < 10; j++) {
        int idx = base + j;
        int c = (idx < NN) ? g_cnt[idx] : 0;
        local[j] = s;
        s += c;
    }
    spart[t] = s;
    __syncthreads();
#pragma unroll
    for (int off = 1; off < 1024; off <<= 1) {
        int v = (t >= off) ? spart[t - off] : 0;
        __syncthreads();
        spart[t] += v;
        __syncthreads();
    }
    int tpre = (t > 0) ? spart[t - 1] : 0;
#pragma unroll
    for (int j = 0; j < 10; j++) {
        int idx = base + j;
        if (idx < NN) {
            int o = tpre + local[j];
            g_off[idx] = o;
            g_cur[idx] = o;
        }
    }
    if (t == 1023) g_off[NN] = spart[1023];
}

__global__ void scatter_kernel(const int* __restrict__ src,
                               const int* __restrict__ dst) {
    int e = blockIdx.x * blockDim.x + threadIdx.x;
    if (e >= NE) return;
    int pos = atomicAdd(&g_cur[src[e]], 1);
    g_edst[pos] = dst[e];
}

// ---------------------------------------------------------------------------
// Merged prep: [0, NN*DM): split x into hi/lo bf16
//              [NN*DM, NN*DM+4*DM*DM): split W (transposed [n][k])
//              [.., +NN): zero g_cnt
// ---------------------------------------------------------------------------
#define PREP_A_END (NN * DM)
#define PREP_W_END (PREP_A_END + 4 * DM * DM)
#define PREP_TOTAL (PREP_W_END + NN)

__global__ void prep_all_kernel(const float* __restrict__ x,
                                const float* __restrict__ Wq,
                                const float* __restrict__ Wk,
                                const float* __restrict__ Wv,
                                const float* __restrict__ Wo) {
    int i = blockIdx.x * blockDim.x + threadIdx.x;
    if (i < PREP_A_END) {
        float v = x[i];
        __nv_bfloat16 hi = __float2bfloat16(v);
        g_Ahi[i] = hi;
        g_Alo[i] = __float2bfloat16(v - __bfloat162float(hi));
    } else if (i < PREP_W_END) {
        int j = i - PREP_A_END;
        int z = j >> 16;
        int r = j & 0xFFFF;
        int k = r >> 8;
        int n = r & 255;
        const float* W = (z == 0) ? Wq : (z == 1) ? Wk : (z == 2) ? Wv : Wo;
        float w = W[k * DM + n];
        __nv_bfloat16 hi = __float2bfloat16(w);
        g_Bhi[z * DM * DM + n * DM + k] = hi;
        g_Blo[z * DM * DM + n * DM + k] = __float2bfloat16(w - __bfloat162float(hi));
    } else if (i < PREP_TOTAL) {
        g_cnt[i - PREP_W_END] = 0;
    }
}

// ---------------------------------------------------------------------------
// Warp-MMA GEMM, cp.async double-buffered:
// C[M,256] = A[M,256] @ W using B[n][k] = W[k][n] (row.col mma, D = A @ B^T).
// Block tile 128x128, 8 warps (2m x 4n), warp tile 64x32, BK=64, 2 stages.
// 3 passes (hh, lh, hl) from registers, single smem fill per k-chunk.
// ---------------------------------------------------------------------------
#define SSTR 72                      // smem row stride (bf16), 144B
#define SM_CHUNK (128 * SSTR)        // one operand chunk (elems)
#define STAGE_ELEMS (4 * SM_CHUNK)   // Ahi|Alo|Bhi|Blo
#define GEMM_SMEM (2 * STAGE_ELEMS * 2)  // bytes = 147456

__global__ void __launch_bounds__(256, 1)
mma_gemm_kernel(const __nv_bfloat16* __restrict__ Ahi,
                const __nv_bfloat16* __restrict__ Alo,
                int zoff,
                float* __restrict__ C0, float* __restrict__ C1,
                float* __restrict__ C2, int M) {
    extern __shared__ __nv_bfloat16 sm[];

    const int tid = threadIdx.x;
    const int wid = tid >> 5;
    const int lane = tid & 31;
    const int wm = wid & 1;
    const int wn = wid >> 1;
    const int z = blockIdx.z;
    float* C = (z == 0) ? C0 : (z == 1) ? C1 : C2;
    const __nv_bfloat16* Bhi = g_Bhi + (size_t)(z + zoff) * DM * DM;
    const __nv_bfloat16* Blo = g_Blo + (size_t)(z + zoff) * DM * DM;
    const int m0 = blockIdx.x * 128;
    const int n0 = blockIdx.y * 128;

    // per-thread load coordinates (16B granules)
    const int l_r = tid >> 3;            // 0..31 (row group of 4)
    const int l_c8 = (tid & 7) << 3;     // 0..56 step 8

    // issue one chunk's loads into stage s
    auto preload = [&](int kc, int s) {
        __nv_bfloat16* base = sm + s * STAGE_ELEMS;
        uint32_t sAhi = smem_u32(base);
        uint32_t sAlo = smem_u32(base + SM_CHUNK);
        uint32_t sBhi = smem_u32(base + 2 * SM_CHUNK);
        uint32_t sBlo = smem_u32(base + 3 * SM_CHUNK);
        const int k0 = kc * 64;
#pragma unroll
        for (int it = 0; it < 4; it++) {
            int r = it * 32 + l_r;
            int gm = m0 + r;
            uint32_t soff = (uint32_t)(r * SSTR + l_c8) * 2;
            uint32_t szA = (gm < M) ? 16u : 0u;
            size_t ga = (size_t)gm * DM + k0 + l_c8;
            cp_async16(sAhi + soff, Ahi + ga, szA);
            cp_async16(sAlo + soff, Alo + ga, szA);
            size_t gb = (size_t)(n0 + r) * DM + k0 + l_c8;
            cp_async16(sBhi + soff, Bhi + gb, 16u);
            cp_async16(sBlo + soff, Blo + gb, 16u);
        }
        cp_commit();
    };

    float acc[4][4][4];
#pragma unroll
    for (int i = 0; i < 4; i++)
#pragma unroll
        for (int j = 0; j < 4; j++)
#pragma unroll
            for (int r = 0; r < 4; r++) acc[i][j][r] = 0.f;

    const int a_r = lane & 15;
    const int a_c = (lane >> 4) << 3;
    const int b_r = lane & 7;
    const int b_c = ((lane >> 3) & 1) << 3;

    preload(0, 0);

#pragma unroll 1
    for (int kc = 0; kc < 4; kc++) {
        if (kc < 3) preload(kc + 1, (kc + 1) & 1);
        if (kc < 3) cp_wait<1>(); else cp_wait<0>();
        __syncthreads();

        __nv_bfloat16* base = sm + (kc & 1) * STAGE_ELEMS;
        __nv_bfloat16* sAhi = base;
        __nv_bfloat16* sAlo = base + SM_CHUNK;
        __nv_bfloat16* sBhi = base + 2 * SM_CHUNK;
        __nv_bfloat16* sBlo = base + 3 * SM_CHUNK;

#pragma unroll
        for (int ks = 0; ks < 4; ks++) {
            const int koff = ks * 16;
            uint32_t ah[4][4], al[4][4];
#pragma unroll
            for (int i = 0; i < 4; i++) {
                int row = wm * 64 + i * 16 + a_r;
                uint32_t addr = smem_u32(&sAhi[row * SSTR + koff + a_c]);
                asm volatile(
                    "ldmatrix.sync.aligned.m8n8.x4.shared.b16 {%0,%1,%2,%3}, [%4];"
                    : "=r"(ah[i][0]), "=r"(ah[i][1]), "=r"(ah[i][2]), "=r"(ah[i][3])
                    : "r"(addr));
                uint32_t addr2 = smem_u32(&sAlo[row * SSTR + koff + a_c]);
                asm volatile(
                    "ldmatrix.sync.aligned.m8n8.x4.shared.b16 {%0,%1,%2,%3}, [%4];"
                    : "=r"(al[i][0]), "=r"(al[i][1]), "=r"(al[i][2]), "=r"(al[i][3])
                    : "r"(addr2));
            }
            uint32_t b[4][2];
#pragma unroll
            for (int j = 0; j < 4; j++) {
                int row = wn * 32 + j * 8 + b_r;
                uint32_t addr = smem_u32(&sBhi[row * SSTR + koff + b_c]);
                asm volatile(
                    "ldmatrix.sync.aligned.m8n8.x2.shared.b16 {%0,%1}, [%2];"
                    : "=r"(b[j][0]), "=r"(b[j][1]) : "r"(addr));
            }
#pragma unroll
            for (int i = 0; i < 4; i++)
#pragma unroll
                for (int j = 0; j < 4; j++)
                    asm volatile(
                        "mma.sync.aligned.m16n8k16.row.col.f32.bf16.bf16.f32 "
                        "{%0,%1,%2,%3}, {%4,%5,%6,%7}, {%8,%9}, {%0,%1,%2,%3};"
                        : "+f"(acc[i][j][0]), "+f"(acc[i][j][1]),
                          "+f"(acc[i][j][2]), "+f"(acc[i][j][3])
                        : "r"(ah[i][0]), "r"(ah[i][1]), "r"(ah[i][2]), "r"(ah[i][3]),
                          "r"(b[j][0]), "r"(b[j][1]));
#pragma unroll
            for (int i = 0; i < 4; i++)
#pragma unroll
                for (int j = 0; j < 4; j++)
                    asm volatile(
                        "mma.sync.aligned.m16n8k16.row.col.f32.bf16.bf16.f32 "
                        "{%0,%1,%2,%3}, {%4,%5,%6,%7}, {%8,%9}, {%0,%1,%2,%3};"
                        : "+f"(acc[i][j][0]), "+f"(acc[i][j][1]),
                          "+f"(acc[i][j][2]), "+f"(acc[i][j][3])
                        : "r"(al[i][0]), "r"(al[i][1]), "r"(al[i][2]), "r"(al[i][3]),
                          "r"(b[j][0]), "r"(b[j][1]));
#pragma unroll
            for (int j = 0; j < 4; j++) {
                int row = wn * 32 + j * 8 + b_r;
                uint32_t addr = smem_u32(&sBlo[row * SSTR + koff + b_c]);
                asm volatile(
                    "ldmatrix.sync.aligned.m8n8.x2.shared.b16 {%0,%1}, [%2];"
                    : "=r"(b[j][0]), "=r"(b[j][1]) : "r"(addr));
            }
#pragma unroll
            for (int i = 0; i < 4; i++)
#pragma unroll
                for (int j = 0; j < 4; j++)
                    asm volatile(
                        "mma.sync.aligned.m16n8k16.row.col.f32.bf16.bf16.f32 "
                        "{%0,%1,%2,%3}, {%4,%5,%6,%7}, {%8,%9}, {%0,%1,%2,%3};"
                        : "+f"(acc[i][j][0]), "+f"(acc[i][j][1]),
                          "+f"(acc[i][j][2]), "+f"(acc[i][j][3])
                        : "r"(ah[i][0]), "r"(ah[i][1]), "r"(ah[i][2]), "r"(ah[i][3]),
                          "r"(b[j][0]), "r"(b[j][1]));
        }
        __syncthreads();
    }

    const int er = lane >> 2;
    const int ec = (lane & 3) << 1;
#pragma unroll
    for (int i = 0; i < 4; i++) {
        int gm0 = m0 + wm * 64 + i * 16 + er;
#pragma unroll
        for (int j = 0; j < 4; j++) {
            int gc = n0 + wn * 32 + j * 8 + ec;
            if (gm0 < M)
                *(float2*)(C + (size_t)gm0 * DM + gc) =
                    make_float2(acc[i][j][0], acc[i][j][1]);
            if (gm0 + 8 < M)
                *(float2*)(C + (size_t)(gm0 + 8) * DM + gc) =
                    make_float2(acc[i][j][2], acc[i][j][3]);
        }
    }
}

// ---------------------------------------------------------------------------
// Node aggregation: warp per node, Q in regs, stream neighbor K/V with
// next-index prefetch, softmax in registers, write hi/lo bf16 directly.
// ---------------------------------------------------------------------------
__global__ void node_agg_kernel() {
    int n = blockIdx.x * (blockDim.x >> 5) + (threadIdx.x >> 5);
    if (n >= NN) return;
    int lane = threadIdx.x & 31;

    const float4* q4 = (const float4*)(g_Q + (size_t)n * DM);
    float4 qa = q4[2 * lane], qb = q4[2 * lane + 1];

    int beg = g_off[n];
    int end = g_off[n + 1];

    float acc[8] = {0.f, 0.f, 0.f, 0.f, 0.f, 0.f, 0.f, 0.f};
    float den = 0.f;

    int d = (beg < end) ? __ldg(&g_edst[beg]) : 0;
#pragma unroll 1
    for (int i = beg; i < end; i++) {
        int dn = (i + 1 < end) ? __ldg(&g_edst[i + 1]) : 0;
        const float4* k4 = (const float4*)(g_K + (size_t)d * DM);
        const float4* v4 = (const float4*)(g_V + (size_t)d * DM);
        float4 ka = k4[2 * lane], kb = k4[2 * lane + 1];
        float4 va = v4[2 * lane], vb = v4[2 * lane + 1];

        float p = qa.x * ka.x + qa.y * ka.y + qa.z * ka.z + qa.w * ka.w +
                  qb.x * kb.x + qb.y * kb.y + qb.z * kb.z + qb.w * kb.w;
        p += __shfl_xor_sync(0xFFFFFFFFu, p, 1);
        p += __shfl_xor_sync(0xFFFFFFFFu, p, 2);

        float ex = __expf(p * SCALE);
        den += ex;
        acc[0] += ex * va.x; acc[1] += ex * va.y;
        acc[2] += ex * va.z; acc[3] += ex * va.w;
        acc[4] += ex * vb.x; acc[5] += ex * vb.y;
        acc[6] += ex * vb.z; acc[7] += ex * vb.w;
        d = dn;
    }

    float inv = (den > 0.f) ? 1.f / den : 0.f;
    __nv_bfloat16 hi8[8], lo8[8];
#pragma unroll
    for (int j = 0; j < 8; j++) {
        float v = acc[j] * inv;
        __nv_bfloat16 hi = __float2bfloat16(v);
        hi8[j] = hi;
        lo8[j] = __float2bfloat16(v - __bfloat162float(hi));
    }
    size_t base = (size_t)n * DM + 8 * lane;
    *(uint4*)(g_Ahi + base) = *(const uint4*)hi8;
    *(uint4*)(g_Alo + base) = *(const uint4*)lo8;
}

// ---------------------------------------------------------------------------
// Residual + LayerNorm, warp per node (no smem, shfl reductions only).
// Lane l owns columns [8l, 8l+8).
// ---------------------------------------------------------------------------
__global__ void ln_kernel(const float* __restrict__ x,
                          const float* __restrict__ gamma,
                          const float* __restrict__ beta,
                          float* __restrict__ out) {
    int n = blockIdx.x * (blockDim.x >> 5) + (threadIdx.x >> 5);
    if (n >= NN) return;
    int lane = threadIdx.x & 31;

    const float4* o4 = (const float4*)(g_out + (size_t)n * DM);
    const float4* x4 = (const float4*)(x + (size_t)n * DM);
    float4 a = o4[2 * lane], b = o4[2 * lane + 1];
    float4 xa = x4[2 * lane], xb = x4[2 * lane + 1];
    float v[8] = {a.x + xa.x, a.y + xa.y, a.z + xa.z, a.w + xa.w,
                  b.x + xb.x, b.y + xb.y, b.z + xb.z, b.w + xb.w};

    float s = 0.f;
#pragma unroll
    for (int j = 0; j < 8; j++) s += v[j];
#pragma unroll
    for (int o = 16; o; o >>= 1) s += __shfl_xor_sync(0xFFFFFFFFu, s, o);
    float mu = s * (1.f / DM);

    float sq = 0.f;
#pragma unroll
    for (int j = 0; j < 8; j++) {
        float dvf = v[j] - mu;
        sq += dvf * dvf;
    }
#pragma unroll
    for (int o = 16; o; o >>= 1) sq += __shfl_xor_sync(0xFFFFFFFFu, sq, o);
    float rstd = rsqrtf(sq * (1.f / DM) + 1e-5f);

    const float4* g4 = (const float4*)gamma;
    const float4* b4 = (const float4*)beta;
    float4 ga = g4[2 * lane], gb = g4[2 * lane + 1];
    float4 ba = b4[2 * lane], bb = b4[2 * lane + 1];

    float4 r0, r1;
    r0.x = (v[0] - mu) * rstd * ga.x + ba.x;
    r0.y = (v[1] - mu) * rstd * ga.y + ba.y;
    r0.z = (v[2] - mu) * rstd * ga.z + ba.z;
    r0.w = (v[3] - mu) * rstd * ga.w + ba.w;
    r1.x = (v[4] - mu) * rstd * gb.x + bb.x;
    r1.y = (v[5] - mu) * rstd * gb.y + bb.y;
    r1.z = (v[6] - mu) * rstd * gb.z + bb.z;
    r1.w = (v[7] - mu) * rstd * gb.w + bb.w;

    float4* out4 = (float4*)(out + (size_t)n * DM);
    out4[2 * lane] = r0;
    out4[2 * lane + 1] = r1;
}

// ---------------------------------------------------------------------------
extern "C" void kernel_launch(void* const* d_in, const int* in_sizes, int n_in,
                              void* d_out, int out_size) {
    const float* x     = (const float*)d_in[0];
    const int*   eidx  = (const int*)d_in[1];
    const float* Wq    = (const float*)d_in[2];
    const float* Wk    = (const float*)d_in[3];
    const float* Wv    = (const float*)d_in[4];
    const float* Wo    = (const float*)d_in[5];
    const float* gamma = (const float*)d_in[6];
    const float* beta  = (const float*)d_in[7];
    float* out = (float*)d_out;

    const int* src = eidx;
    const int* dst = eidx + NE;

    float* Qp = nullptr; cudaGetSymbolAddress((void**)&Qp, g_Q);
    float* Kp = nullptr; cudaGetSymbolAddress((void**)&Kp, g_K);
    float* Vp = nullptr; cudaGetSymbolAddress((void**)&Vp, g_V);
    float* Op = nullptr; cudaGetSymbolAddress((void**)&Op, g_out);
    __nv_bfloat16* Ahip = nullptr; cudaGetSymbolAddress((void**)&Ahip, g_Ahi);
    __nv_bfloat16* Alop = nullptr; cudaGetSymbolAddress((void**)&Alop, g_Alo);

    cudaFuncSetAttribute(mma_gemm_kernel,
                         cudaFuncAttributeMaxDynamicSharedMemorySize, GEMM_SMEM);

    // merged prep: x hi/lo, W hi/lo transposed, zero cnt
    prep_all_kernel<<<(PREP_TOTAL + 255) / 256, 256>>>(x, Wq, Wk, Wv, Wo);

    // CSR build
    hist_kernel<<<(NE + 255) / 256, 256>>>(src);
    scan_kernel<<<1, 1024>>>();
    scatter_kernel<<<(NE + 255) / 256, 256>>>(src, dst);

    // QKV tensor-core GEMMs (z selects matrix)
    dim3 gq((NN + 127) / 128, DM / 128, 3);
    mma_gemm_kernel<<<gq, 256, GEMM_SMEM>>>(Ahip, Alop, 0, Qp, Kp, Vp, NN);

    // per-node softmax aggregation (writes Ahi/Alo directly)
    node_agg_kernel<<<(NN + 7) / 8, 256>>>();

    // output GEMM: g_out = (agg/denom) @ Wo
    dim3 go((NN + 127) / 128, DM / 128, 1);
    mma_gemm_kernel<<<go, 256, GEMM_SMEM>>>(Ahip, Alop, 3, Op, Op, Op, NN);

    // residual + LayerNorm (warp per node)
    ln_kernel<<<(NN + 7) / 8, 256>>>(x, gamma, beta, out);
}

// round 7
// speedup vs baseline: 1.8431x; 1.1232x over previous
#include <cuda_runtime.h>
#include <cuda_bf16.h>
#include <cstdint>

#define NN 10000
#define NE 160000
#define DM 256
#define NH 8
#define HD 32
#define SCALE 0.17677669529663687f  // 1/sqrt(32)

// ---------------- device scratch (no dynamic allocation allowed) ------------
__device__ float g_Q[NN * DM];
__device__ float g_K[NN * DM];
__device__ float g_V[NN * DM];
__device__ float g_out[NN * DM];

// bf16 two-term split operands for tensor-core GEMMs
__device__ __nv_bfloat16 g_Ahi[NN * DM];
__device__ __nv_bfloat16 g_Alo[NN * DM];
// W matrices transposed: g_B*[z][n][k] = W_z[k][n], z in {q,k,v,o}
__device__ __nv_bfloat16 g_Bhi[4 * DM * DM];
__device__ __nv_bfloat16 g_Blo[4 * DM * DM];

// CSR over src
__device__ int g_cnt[NN];
__device__ int g_off[NN + 1];
__device__ int g_cur[NN];
__device__ int g_edst[NE];

__device__ __forceinline__ uint32_t smem_u32(const void* p) {
    uint32_t a;
    asm("{ .reg .u64 t; cvta.to.shared.u64 t, %1; cvt.u32.u64 %0, t; }"
        : "=r"(a) : "l"(p));
    return a;
}

__device__ __forceinline__ void cp_async16(uint32_t saddr, const void* gaddr,
                                           uint32_t src_sz) {
    asm volatile("cp.async.cg.shared.global [%0], [%1], 16, %2;"
                 :: "r"(saddr), "l"(gaddr), "r"(src_sz));
}
__device__ __forceinline__ void cp_commit() {
    asm volatile("cp.async.commit_group;" ::: "memory");
}
template <int N>
__device__ __forceinline__ void cp_wait() {
    asm volatile("cp.async.wait_group %0;" :: "n"(N) : "memory");
}

// ---------------------------------------------------------------------------
// CSR build: histogram, scan, scatter
// ---------------------------------------------------------------------------
__global__ void hist_kernel(const int* __restrict__ src) {
    int e = blockIdx.x * blockDim.x + threadIdx.x;
    if (e < NE) atomicAdd(&g_cnt[src[e]], 1);
}

// One-CTA scan: 1024 threads, each owns 10 consecutive counts.
__global__ void scan_kernel() {
    __shared__ int spart[1024];
    int t = threadIdx.x;
    int base = t * 10;
    int local[10];
    int s = 0;
#pragma unroll
    for (int j = 0; j < 10; j++) {
        int idx = base + j;
        int c = (idx < NN) ? g_cnt[idx] : 0;
        local[j] = s;
        s += c;
    }
    spart[t] = s;
    __syncthreads();
#pragma unroll
    for (int off = 1; off < 1024; off <<= 1) {
        int v = (t >= off) ? spart[t - off] : 0;
        __syncthreads();
        spart[t] += v;
        __syncthreads();
    }
    int tpre = (t > 0) ? spart[t - 1] : 0;
#pragma unroll
    for (int j = 0; j < 10; j++) {
        int idx = base + j;
        if (idx < NN) {
            int o = tpre + local[j];
            g_off[idx] = o;
            g_cur[idx] = o;
        }
    }
    if (t == 1023) g_off[NN] = spart[1023];
}

__global__ void scatter_kernel(const int* __restrict__ src,
                               const int* __restrict__ dst) {
    int e = blockIdx.x * blockDim.x + threadIdx.x;
    if (e >= NE) return;
    int pos = atomicAdd(&g_cur[src[e]], 1);
    g_edst[pos] = dst[e];
}

// ---------------------------------------------------------------------------
// Merged prep: [0, NN*DM): split x into hi/lo bf16
//              [NN*DM, NN*DM+4*DM*DM): split W (transposed [n][k])
//              [.., +NN): zero g_cnt
// ---------------------------------------------------------------------------
#define PREP_A_END (NN * DM)
#define PREP_W_END (PREP_A_END + 4 * DM * DM)
#define PREP_TOTAL (PREP_W_END + NN)

__global__ void prep_all_kernel(const float* __restrict__ x,
                                const float* __restrict__ Wq,
                                const float* __restrict__ Wk,
                                const float* __restrict__ Wv,
                                const float* __restrict__ Wo) {
    int i = blockIdx.x * blockDim.x + threadIdx.x;
    if (i < PREP_A_END) {
        float v = x[i];
        __nv_bfloat16 hi = __float2bfloat16(v);
        g_Ahi[i] = hi;
        g_Alo[i] = __float2bfloat16(v - __bfloat162float(hi));
    } else if (i < PREP_W_END) {
        int j = i - PREP_A_END;
        int z = j >> 16;
        int r = j & 0xFFFF;
        int k = r >> 8;
        int n = r & 255;
        const float* W = (z == 0) ? Wq : (z == 1) ? Wk : (z == 2) ? Wv : Wo;
        float w = W[k * DM + n];
        __nv_bfloat16 hi = __float2bfloat16(w);
        g_Bhi[z * DM * DM + n * DM + k] = hi;
        g_Blo[z * DM * DM + n * DM + k] = __float2bfloat16(w - __bfloat162float(hi));
    } else if (i < PREP_TOTAL) {
        g_cnt[i - PREP_W_END] = 0;
    }
}

// ---------------------------------------------------------------------------
// Warp-MMA GEMM, cp.async double-buffered, BK=32 (2 CTAs/SM, 16 warps):
// C[M,256] = A[M,256] @ W using B[n][k] = W[k][n] (row.col mma, D = A @ B^T).
// Block tile 128x128, 8 warps (2m x 4n), warp tile 64x32, 8 k-chunks of 32.
// 3 passes (hh, lh, hl) from registers, single smem fill per k-chunk.
// ---------------------------------------------------------------------------
#define SSTR 40                      // smem row stride (bf16), 80B
#define SM_CHUNK (128 * SSTR)        // one operand chunk (elems)
#define STAGE_ELEMS (4 * SM_CHUNK)   // Ahi|Alo|Bhi|Blo
#define GEMM_SMEM (2 * STAGE_ELEMS * 2)  // bytes = 81920

__global__ void __launch_bounds__(256, 2)
mma_gemm_kernel(const __nv_bfloat16* __restrict__ Ahi,
                const __nv_bfloat16* __restrict__ Alo,
                int zoff,
                float* __restrict__ C0, float* __restrict__ C1,
                float* __restrict__ C2, int M) {
    extern __shared__ __nv_bfloat16 sm[];

    const int tid = threadIdx.x;
    const int wid = tid >> 5;
    const int lane = tid & 31;
    const int wm = wid & 1;
    const int wn = wid >> 1;
    const int z = blockIdx.z;
    float* C = (z == 0) ? C0 : (z == 1) ? C1 : C2;
    const __nv_bfloat16* Bhi = g_Bhi + (size_t)(z + zoff) * DM * DM;
    const __nv_bfloat16* Blo = g_Blo + (size_t)(z + zoff) * DM * DM;
    const int m0 = blockIdx.x * 128;
    const int n0 = blockIdx.y * 128;

    // per-thread load coordinates: 4 granules(16B)/row, 64 rows per iter
    const int l_r = tid >> 2;            // 0..63
    const int l_c8 = (tid & 3) << 3;     // 0,8,16,24 (elems)

    auto preload = [&](int kc, int s) {
        __nv_bfloat16* base = sm + s * STAGE_ELEMS;
        uint32_t sAhi = smem_u32(base);
        uint32_t sAlo = smem_u32(base + SM_CHUNK);
        uint32_t sBhi = smem_u32(base + 2 * SM_CHUNK);
        uint32_t sBlo = smem_u32(base + 3 * SM_CHUNK);
        const int k0 = kc * 32;
#pragma unroll
        for (int it = 0; it < 2; it++) {
            int r = it * 64 + l_r;
            int gm = m0 + r;
            uint32_t soff = (uint32_t)(r * SSTR + l_c8) * 2;
            uint32_t szA = (gm < M) ? 16u : 0u;
            size_t ga = (size_t)gm * DM + k0 + l_c8;
            cp_async16(sAhi + soff, Ahi + ga, szA);
            cp_async16(sAlo + soff, Alo + ga, szA);
            size_t gb = (size_t)(n0 + r) * DM + k0 + l_c8;
            cp_async16(sBhi + soff, Bhi + gb, 16u);
            cp_async16(sBlo + soff, Blo + gb, 16u);
        }
        cp_commit();
    };

    float acc[4][4][4];
#pragma unroll
    for (int i = 0; i < 4; i++)
#pragma unroll
        for (int j = 0; j < 4; j++)
#pragma unroll
            for (int r = 0; r < 4; r++) acc[i][j][r] = 0.f;

    const int a_r = lane & 15;
    const int a_c = (lane >> 4) << 3;
    const int b_r = lane & 7;
    const int b_c = ((lane >> 3) & 1) << 3;

    preload(0, 0);

#pragma unroll 1
    for (int kc = 0; kc < 8; kc++) {
        if (kc < 7) {
            preload(kc + 1, (kc + 1) & 1);
            cp_wait<1>();
        } else {
            cp_wait<0>();
        }
        __syncthreads();

        __nv_bfloat16* base = sm + (kc & 1) * STAGE_ELEMS;
        __nv_bfloat16* sAhi = base;
        __nv_bfloat16* sAlo = base + SM_CHUNK;
        __nv_bfloat16* sBhi = base + 2 * SM_CHUNK;
        __nv_bfloat16* sBlo = base + 3 * SM_CHUNK;

#pragma unroll
        for (int ks = 0; ks < 2; ks++) {
            const int koff = ks * 16;
            uint32_t ah[4][4], al[4][4];
#pragma unroll
            for (int i = 0; i < 4; i++) {
                int row = wm * 64 + i * 16 + a_r;
                uint32_t addr = smem_u32(&sAhi[row * SSTR + koff + a_c]);
                asm volatile(
                    "ldmatrix.sync.aligned.m8n8.x4.shared.b16 {%0,%1,%2,%3}, [%4];"
                    : "=r"(ah[i][0]), "=r"(ah[i][1]), "=r"(ah[i][2]), "=r"(ah[i][3])
                    : "r"(addr));
                uint32_t addr2 = smem_u32(&sAlo[row * SSTR + koff + a_c]);
                asm volatile(
                    "ldmatrix.sync.aligned.m8n8.x4.shared.b16 {%0,%1,%2,%3}, [%4];"
                    : "=r"(al[i][0]), "=r"(al[i][1]), "=r"(al[i][2]), "=r"(al[i][3])
                    : "r"(addr2));
            }
            uint32_t b[4][2];
#pragma unroll
            for (int j = 0; j < 4; j++) {
                int row = wn * 32 + j * 8 + b_r;
                uint32_t addr = smem_u32(&sBhi[row * SSTR + koff + b_c]);
                asm volatile(
                    "ldmatrix.sync.aligned.m8n8.x2.shared.b16 {%0,%1}, [%2];"
                    : "=r"(b[j][0]), "=r"(b[j][1]) : "r"(addr));
            }
#pragma unroll
            for (int i = 0; i < 4; i++)
#pragma unroll
                for (int j = 0; j < 4; j++)
                    asm volatile(
                        "mma.sync.aligned.m16n8k16.row.col.f32.bf16.bf16.f32 "
                        "{%0,%1,%2,%3}, {%4,%5,%6,%7}, {%8,%9}, {%0,%1,%2,%3};"
                        : "+f"(acc[i][j][0]), "+f"(acc[i][j][1]),
                          "+f"(acc[i][j][2]), "+f"(acc[i][j][3])
                        : "r"(ah[i][0]), "r"(ah[i][1]), "r"(ah[i][2]), "r"(ah[i][3]),
                          "r"(b[j][0]), "r"(b[j][1]));
#pragma unroll
            for (int i = 0; i < 4; i++)
#pragma unroll
                for (int j = 0; j < 4; j++)
                    asm volatile(
                        "mma.sync.aligned.m16n8k16.row.col.f32.bf16.bf16.f32 "
                        "{%0,%1,%2,%3}, {%4,%5,%6,%7}, {%8,%9}, {%0,%1,%2,%3};"
                        : "+f"(acc[i][j][0]), "+f"(acc[i][j][1]),
                          "+f"(acc[i][j][2]), "+f"(acc[i][j][3])
                        : "r"(al[i][0]), "r"(al[i][1]), "r"(al[i][2]), "r"(al[i][3]),
                          "r"(b[j][0]), "r"(b[j][1]));
#pragma unroll
            for (int j = 0; j < 4; j++) {
                int row = wn * 32 + j * 8 + b_r;
                uint32_t addr = smem_u32(&sBlo[row * SSTR + koff + b_c]);
                asm volatile(
                    "ldmatrix.sync.aligned.m8n8.x2.shared.b16 {%0,%1}, [%2];"
                    : "=r"(b[j][0]), "=r"(b[j][1]) : "r"(addr));
            }
#pragma unroll
            for (int i = 0; i < 4; i++)
#pragma unroll
                for (int j = 0; j < 4; j++)
                    asm volatile(
                        "mma.sync.aligned.m16n8k16.row.col.f32.bf16.bf16.f32 "
                        "{%0,%1,%2,%3}, {%4,%5,%6,%7}, {%8,%9}, {%0,%1,%2,%3};"
                        : "+f"(acc[i][j][0]), "+f"(acc[i][j][1]),
                          "+f"(acc[i][j][2]), "+f"(acc[i][j][3])
                        : "r"(ah[i][0]), "r"(ah[i][1]), "r"(ah[i][2]), "r"(ah[i][3]),
                          "r"(b[j][0]), "r"(b[j][1]));
        }
        __syncthreads();
    }

    const int er = lane >> 2;
    const int ec = (lane & 3) << 1;
#pragma unroll
    for (int i = 0; i < 4; i++) {
        int gm0 = m0 + wm * 64 + i * 16 + er;
#pragma unroll
        for (int j = 0; j < 4; j++) {
            int gc = n0 + wn * 32 + j * 8 + ec;
            if (gm0 < M)
                *(float2*)(C + (size_t)gm0 * DM + gc) =
                    make_float2(acc[i][j][0], acc[i][j][1]);
            if (gm0 + 8 < M)
                *(float2*)(C + (size_t)(gm0 + 8) * DM + gc) =
                    make_float2(acc[i][j][2], acc[i][j][3]);
        }
    }
}

// ---------------------------------------------------------------------------
// Node aggregation: warp per node, Q in regs, stream neighbor K/V with
// next-index prefetch, softmax in registers, write hi/lo bf16 directly.
// ---------------------------------------------------------------------------
__global__ void node_agg_kernel() {
    int n = blockIdx.x * (blockDim.x >> 5) + (threadIdx.x >> 5);
    if (n >= NN) return;
    int lane = threadIdx.x & 31;

    const float4* q4 = (const float4*)(g_Q + (size_t)n * DM);
    float4 qa = q4[2 * lane], qb = q4[2 * lane + 1];

    int beg = g_off[n];
    int end = g_off[n + 1];

    float acc[8] = {0.f, 0.f, 0.f, 0.f, 0.f, 0.f, 0.f, 0.f};
    float den = 0.f;

    int d = (beg < end) ? __ldg(&g_edst[beg]) : 0;
#pragma unroll 1
    for (int i = beg; i < end; i++) {
        int dn = (i + 1 < end) ? __ldg(&g_edst[i + 1]) : 0;
        const float4* k4 = (const float4*)(g_K + (size_t)d * DM);
        const float4* v4 = (const float4*)(g_V + (size_t)d * DM);
        float4 ka = k4[2 * lane], kb = k4[2 * lane + 1];
        float4 va = v4[2 * lane], vb = v4[2 * lane + 1];

        float p = qa.x * ka.x + qa.y * ka.y + qa.z * ka.z + qa.w * ka.w +
                  qb.x * kb.x + qb.y * kb.y + qb.z * kb.z + qb.w * kb.w;
        p += __shfl_xor_sync(0xFFFFFFFFu, p, 1);
        p += __shfl_xor_sync(0xFFFFFFFFu, p, 2);

        float ex = __expf(p * SCALE);
        den += ex;
        acc[0] += ex * va.x; acc[1] += ex * va.y;
        acc[2] += ex * va.z; acc[3] += ex * va.w;
        acc[4] += ex * vb.x; acc[5] += ex * vb.y;
        acc[6] += ex * vb.z; acc[7] += ex * vb.w;
        d = dn;
    }

    float inv = (den > 0.f) ? 1.f / den : 0.f;
    __nv_bfloat16 hi8[8], lo8[8];
#pragma unroll
    for (int j = 0; j < 8; j++) {
        float v = acc[j] * inv;
        __nv_bfloat16 hi = __float2bfloat16(v);
        hi8[j] = hi;
        lo8[j] = __float2bfloat16(v - __bfloat162float(hi));
    }
    size_t base = (size_t)n * DM + 8 * lane;
    *(uint4*)(g_Ahi + base) = *(const uint4*)hi8;
    *(uint4*)(g_Alo + base) = *(const uint4*)lo8;
}

// ---------------------------------------------------------------------------
// Residual + LayerNorm, warp per node (no smem, shfl reductions only).
// ---------------------------------------------------------------------------
__global__ void ln_kernel(const float* __restrict__ x,
                          const float* __restrict__ gamma,
                          const float* __restrict__ beta,
                          float* __restrict__ out) {
    int n = blockIdx.x * (blockDim.x >> 5) + (threadIdx.x >> 5);
    if (n >= NN) return;
    int lane = threadIdx.x & 31;

    const float4* o4 = (const float4*)(g_out + (size_t)n * DM);
    const float4* x4 = (const float4*)(x + (size_t)n * DM);
    float4 a = o4[2 * lane], b = o4[2 * lane + 1];
    float4 xa = x4[2 * lane], xb = x4[2 * lane + 1];
    float v[8] = {a.x + xa.x, a.y + xa.y, a.z + xa.z, a.w + xa.w,
                  b.x + xb.x, b.y + xb.y, b.z + xb.z, b.w + xb.w};

    float s = 0.f;
#pragma unroll
    for (int j = 0; j < 8; j++) s += v[j];
#pragma unroll
    for (int o = 16; o; o >>= 1) s += __shfl_xor_sync(0xFFFFFFFFu, s, o);
    float mu = s * (1.f / DM);

    float sq = 0.f;
#pragma unroll
    for (int j = 0; j < 8; j++) {
        float dvf = v[j] - mu;
        sq += dvf * dvf;
    }
#pragma unroll
    for (int o = 16; o; o >>= 1) sq += __shfl_xor_sync(0xFFFFFFFFu, sq, o);
    float rstd = rsqrtf(sq * (1.f / DM) + 1e-5f);

    const float4* g4 = (const float4*)gamma;
    const float4* b4 = (const float4*)beta;
    float4 ga = g4[2 * lane], gb = g4[2 * lane + 1];
    float4 ba = b4[2 * lane], bb = b4[2 * lane + 1];

    float4 r0, r1;
    r0.x = (v[0] - mu) * rstd * ga.x + ba.x;
    r0.y = (v[1] - mu) * rstd * ga.y + ba.y;
    r0.z = (v[2] - mu) * rstd * ga.z + ba.z;
    r0.w = (v[3] - mu) * rstd * ga.w + ba.w;
    r1.x = (v[4] - mu) * rstd * gb.x + bb.x;
    r1.y = (v[5] - mu) * rstd * gb.y + bb.y;
    r1.z = (v[6] - mu) * rstd * gb.z + bb.z;
    r1.w = (v[7] - mu) * rstd * gb.w + bb.w;

    float4* out4 = (float4*)(out + (size_t)n * DM);
    out4[2 * lane] = r0;
    out4[2 * lane + 1] = r1;
}

// ---------------------------------------------------------------------------
extern "C" void kernel_launch(void* const* d_in, const int* in_sizes, int n_in,
                              void* d_out, int out_size) {
    const float* x     = (const float*)d_in[0];
    const int*   eidx  = (const int*)d_in[1];
    const float* Wq    = (const float*)d_in[2];
    const float* Wk    = (const float*)d_in[3];
    const float* Wv    = (const float*)d_in[4];
    const float* Wo    = (const float*)d_in[5];
    const float* gamma = (const float*)d_in[6];
    const float* beta  = (const float*)d_in[7];
    float* out = (float*)d_out;

    const int* src = eidx;
    const int* dst = eidx + NE;

    float* Qp = nullptr; cudaGetSymbolAddress((void**)&Qp, g_Q);
    float* Kp = nullptr; cudaGetSymbolAddress((void**)&Kp, g_K);
    float* Vp = nullptr; cudaGetSymbolAddress((void**)&Vp, g_V);
    float* Op = nullptr; cudaGetSymbolAddress((void**)&Op, g_out);
    __nv_bfloat16* Ahip = nullptr; cudaGetSymbolAddress((void**)&Ahip, g_Ahi);
    __nv_bfloat16* Alop = nullptr; cudaGetSymbolAddress((void**)&Alop, g_Alo);

    cudaFuncSetAttribute(mma_gemm_kernel,
                         cudaFuncAttributeMaxDynamicSharedMemorySize, GEMM_SMEM);

    // side stream + fork/join events (handles created once; no device mem)
    static cudaStream_t s2 = nullptr;
    static cudaEvent_t eA = nullptr, eB = nullptr;
    if (s2 == nullptr) {
        cudaStreamCreateWithFlags(&s2, cudaStreamNonBlocking);
        cudaEventCreateWithFlags(&eA, cudaEventDisableTiming);
        cudaEventCreateWithFlags(&eB, cudaEventDisableTiming);
    }

    // merged prep: x hi/lo, W hi/lo transposed, zero cnt
    prep_all_kernel<<<(PREP_TOTAL + 255) / 256, 256>>>(x, Wq, Wk, Wv, Wo);
    cudaEventRecord(eA, 0);

    // QKV tensor-core GEMMs on main stream (z selects matrix)
    dim3 gq((NN + 127) / 128, DM / 128, 3);
    mma_gemm_kernel<<<gq, 256, GEMM_SMEM>>>(Ahip, Alop, 0, Qp, Kp, Vp, NN);

    // CSR build on side stream, concurrent with QKV GEMM
    cudaStreamWaitEvent(s2, eA, 0);
    hist_kernel<<<(NE + 255) / 256, 256, 0, s2>>>(src);
    scan_kernel<<<1, 1024, 0, s2>>>();
    scatter_kernel<<<(NE + 255) / 256, 256, 0, s2>>>(src, dst);
    cudaEventRecord(eB, s2);

    // join: aggregation needs both QKV (main) and CSR (side)
    cudaStreamWaitEvent(0, eB, 0);
    node_agg_kernel<<<(NN + 7) / 8, 256>>>();

    // output GEMM: g_out = (agg/denom) @ Wo
    dim3 go((NN + 127) / 128, DM / 128, 1);
    mma_gemm_kernel<<<go, 256, GEMM_SMEM>>>(Ahip, Alop, 3, Op, Op, Op, NN);

    // residual + LayerNorm (warp per node)
    ln_kernel<<<(NN + 7) / 8, 256>>>(x, gamma, beta, out);
}

// round 8
// speedup vs baseline: 1.8697x; 1.0144x over previous
#include <cuda_runtime.h>
#include <cuda_bf16.h>
#include <cstdint>

#define NN 10000
#define NE 160000
#define DM 256
#define NH 8
#define HD 32
#define SCALE 0.17677669529663687f  // 1/sqrt(32)

// ---------------- device scratch (no dynamic allocation allowed) ------------
__device__ float g_Q[NN * DM];
__device__ float g_K[NN * DM];
__device__ float g_V[NN * DM];

// bf16 two-term split operands for tensor-core GEMMs
__device__ __nv_bfloat16 g_Ahi[NN * DM];
__device__ __nv_bfloat16 g_Alo[NN * DM];
// W matrices transposed: g_B*[z][n][k] = W_z[k][n], z in {q,k,v,o}
__device__ __nv_bfloat16 g_Bhi[4 * DM * DM];
__device__ __nv_bfloat16 g_Blo[4 * DM * DM];

// CSR over src
__device__ int g_cnt[NN];
__device__ int g_off[NN + 1];
__device__ int g_cur[NN];
__device__ int g_edst[NE];

__device__ __forceinline__ uint32_t smem_u32(const void* p) {
    uint32_t a;
    asm("{ .reg .u64 t; cvta.to.shared.u64 t, %1; cvt.u32.u64 %0, t; }"
        : "=r"(a) : "l"(p));
    return a;
}

__device__ __forceinline__ void cp_async16(uint32_t saddr, const void* gaddr,
                                           uint32_t src_sz) {
    asm volatile("cp.async.cg.shared.global [%0], [%1], 16, %2;"
                 :: "r"(saddr), "l"(gaddr), "r"(src_sz));
}
__device__ __forceinline__ void cp_commit() {
    asm volatile("cp.async.commit_group;" ::: "memory");
}
template <int N>
__device__ __forceinline__ void cp_wait() {
    asm volatile("cp.async.wait_group %0;" :: "n"(N) : "memory");
}

// ---------------------------------------------------------------------------
// CSR build: histogram, scan (shfl-based), scatter
// ---------------------------------------------------------------------------
__global__ void hist_kernel(const int* __restrict__ src) {
    int e = blockIdx.x * blockDim.x + threadIdx.x;
    if (e < NE) atomicAdd(&g_cnt[src[e]], 1);
}

// One-CTA scan, 1024 threads, each owns 10 counts. Warp shfl scan + one
// cross-warp scan; only 2 block syncs.
__global__ void scan_kernel() {
    __shared__ int wsum[32];
    int t = threadIdx.x;
    int lane = t & 31;
    int warp = t >> 5;
    int base = t * 10;

    int local[10];
    int s = 0;
#pragma unroll
    for (int j = 0; j < 10; j++) {
        int idx = base + j;
        int c = (idx < NN) ? g_cnt[idx] : 0;
        local[j] = s;
        s += c;
    }
    // inclusive warp scan of s
    int inc = s;
#pragma unroll
    for (int o = 1; o < 32; o <<= 1) {
        int v = __shfl_up_sync(0xFFFFFFFFu, inc, o);
        if (lane >= o) inc += v;
    }
    if (lane == 31) wsum[warp] = inc;
    __syncthreads();
    if (warp == 0) {
        int w = wsum[lane];
        int wi = w;
#pragma unroll
        for (int o = 1; o < 32; o <<= 1) {
            int v = __shfl_up_sync(0xFFFFFFFFu, wi, o);
            if (lane >= o) wi += v;
        }
        wsum[lane] = wi - w;  // exclusive
    }
    __syncthreads();
    int texcl = wsum[warp] + (inc - s);  // exclusive prefix for this thread
#pragma unroll
    for (int j = 0; j < 10; j++) {
        int idx = base + j;
        if (idx < NN) {
            int o = texcl + local[j];
            g_off[idx] = o;
            g_cur[idx] = o;
        }
    }
    if (t == 1023) g_off[NN] = texcl + s;
}

__global__ void scatter_kernel(const int* __restrict__ src,
                               const int* __restrict__ dst) {
    int e = blockIdx.x * blockDim.x + threadIdx.x;
    if (e >= NE) return;
    int pos = atomicAdd(&g_cur[src[e]], 1);
    g_edst[pos] = dst[e];
}

// ---------------------------------------------------------------------------
// Merged prep: x hi/lo split, W hi/lo transposed split, zero g_cnt
// ---------------------------------------------------------------------------
#define PREP_A_END (NN * DM)
#define PREP_W_END (PREP_A_END + 4 * DM * DM)
#define PREP_TOTAL (PREP_W_END + NN)

__global__ void prep_all_kernel(const float* __restrict__ x,
                                const float* __restrict__ Wq,
                                const float* __restrict__ Wk,
                                const float* __restrict__ Wv,
                                const float* __restrict__ Wo) {
    int i = blockIdx.x * blockDim.x + threadIdx.x;
    if (i < PREP_A_END) {
        float v = x[i];
        __nv_bfloat16 hi = __float2bfloat16(v);
        g_Ahi[i] = hi;
        g_Alo[i] = __float2bfloat16(v - __bfloat162float(hi));
    } else if (i < PREP_W_END) {
        int j = i - PREP_A_END;
        int z = j >> 16;
        int r = j & 0xFFFF;
        int k = r >> 8;
        int n = r & 255;
        const float* W = (z == 0) ? Wq : (z == 1) ? Wk : (z == 2) ? Wv : Wo;
        float w = W[k * DM + n];
        __nv_bfloat16 hi = __float2bfloat16(w);
        g_Bhi[z * DM * DM + n * DM + k] = hi;
        g_Blo[z * DM * DM + n * DM + k] = __float2bfloat16(w - __bfloat162float(hi));
    } else if (i < PREP_TOTAL) {
        g_cnt[i - PREP_W_END] = 0;
    }
}

// ---------------------------------------------------------------------------
// QKV warp-MMA GEMM, cp.async double-buffered, BK=32 (2 CTAs/SM):
// block 128x128, 8 warps (2m x 4n), warp tile 64x32, 8 k-chunks.
// 3 passes (hh, lh, hl) from registers.
// ---------------------------------------------------------------------------
#define SSTR 40                      // smem row stride (bf16), 80B
#define SM_CHUNK (128 * SSTR)
#define STAGE_ELEMS (4 * SM_CHUNK)
#define GEMM_SMEM (2 * STAGE_ELEMS * 2)  // 81920 B

#define LDSM_X4(r0, r1, r2, r3, addr) \
    asm volatile("ldmatrix.sync.aligned.m8n8.x4.shared.b16 {%0,%1,%2,%3}, [%4];" \
                 : "=r"(r0), "=r"(r1), "=r"(r2), "=r"(r3) : "r"(addr))
#define LDSM_X2(r0, r1, addr) \
    asm volatile("ldmatrix.sync.aligned.m8n8.x2.shared.b16 {%0,%1}, [%2];" \
                 : "=r"(r0), "=r"(r1) : "r"(addr))
#define MMA_BF16(acc, a, b0, b1) \
    asm volatile("mma.sync.aligned.m16n8k16.row.col.f32.bf16.bf16.f32 " \
                 "{%0,%1,%2,%3}, {%4,%5,%6,%7}, {%8,%9}, {%0,%1,%2,%3};" \
                 : "+f"((acc)[0]), "+f"((acc)[1]), "+f"((acc)[2]), "+f"((acc)[3]) \
                 : "r"((a)[0]), "r"((a)[1]), "r"((a)[2]), "r"((a)[3]), \
                   "r"(b0), "r"(b1))

__global__ void __launch_bounds__(256, 2)
mma_gemm_kernel(const __nv_bfloat16* __restrict__ Ahi,
                const __nv_bfloat16* __restrict__ Alo,
                float* __restrict__ C0, float* __restrict__ C1,
                float* __restrict__ C2, int M) {
    extern __shared__ __nv_bfloat16 sm[];

    const int tid = threadIdx.x;
    const int wid = tid >> 5;
    const int lane = tid & 31;
    const int wm = wid & 1;
    const int wn = wid >> 1;
    const int z = blockIdx.z;
    float* C = (z == 0) ? C0 : (z == 1) ? C1 : C2;
    const __nv_bfloat16* Bhi = g_Bhi + (size_t)z * DM * DM;
    const __nv_bfloat16* Blo = g_Blo + (size_t)z * DM * DM;
    const int m0 = blockIdx.x * 128;
    const int n0 = blockIdx.y * 128;

    const int l_r = tid >> 2;
    const int l_c8 = (tid & 3) << 3;

    auto preload = [&](int kc, int s) {
        __nv_bfloat16* base = sm + s * STAGE_ELEMS;
        uint32_t sAhi = smem_u32(base);
        uint32_t sAlo = smem_u32(base + SM_CHUNK);
        uint32_t sBhi = smem_u32(base + 2 * SM_CHUNK);
        uint32_t sBlo = smem_u32(base + 3 * SM_CHUNK);
        const int k0 = kc * 32;
#pragma unroll
        for (int it = 0; it < 2; it++) {
            int r = it * 64 + l_r;
            int gm = m0 + r;
            uint32_t soff = (uint32_t)(r * SSTR + l_c8) * 2;
            uint32_t szA = (gm < M) ? 16u : 0u;
            size_t ga = (size_t)gm * DM + k0 + l_c8;
            cp_async16(sAhi + soff, Ahi + ga, szA);
            cp_async16(sAlo + soff, Alo + ga, szA);
            size_t gb = (size_t)(n0 + r) * DM + k0 + l_c8;
            cp_async16(sBhi + soff, Bhi + gb, 16u);
            cp_async16(sBlo + soff, Blo + gb, 16u);
        }
        cp_commit();
    };

    float acc[4][4][4];
#pragma unroll
    for (int i = 0; i < 4; i++)
#pragma unroll
        for (int j = 0; j < 4; j++)
#pragma unroll
            for (int r = 0; r < 4; r++) acc[i][j][r] = 0.f;

    const int a_r = lane & 15;
    const int a_c = (lane >> 4) << 3;
    const int b_r = lane & 7;
    const int b_c = ((lane >> 3) & 1) << 3;

    preload(0, 0);

#pragma unroll 1
    for (int kc = 0; kc < 8; kc++) {
        if (kc < 7) {
            preload(kc + 1, (kc + 1) & 1);
            cp_wait<1>();
        } else {
            cp_wait<0>();
        }
        __syncthreads();

        __nv_bfloat16* base = sm + (kc & 1) * STAGE_ELEMS;
        __nv_bfloat16* sAhi = base;
        __nv_bfloat16* sAlo = base + SM_CHUNK;
        __nv_bfloat16* sBhi = base + 2 * SM_CHUNK;
        __nv_bfloat16* sBlo = base + 3 * SM_CHUNK;

#pragma unroll
        for (int ks = 0; ks < 2; ks++) {
            const int koff = ks * 16;
            uint32_t ah[4][4], al[4][4];
#pragma unroll
            for (int i = 0; i < 4; i++) {
                int row = wm * 64 + i * 16 + a_r;
                LDSM_X4(ah[i][0], ah[i][1], ah[i][2], ah[i][3],
                        smem_u32(&sAhi[row * SSTR + koff + a_c]));
                LDSM_X4(al[i][0], al[i][1], al[i][2], al[i][3],
                        smem_u32(&sAlo[row * SSTR + koff + a_c]));
            }
            uint32_t b[4][2];
#pragma unroll
            for (int j = 0; j < 4; j++) {
                int row = wn * 32 + j * 8 + b_r;
                LDSM_X2(b[j][0], b[j][1],
                        smem_u32(&sBhi[row * SSTR + koff + b_c]));
            }
#pragma unroll
            for (int i = 0; i < 4; i++)
#pragma unroll
                for (int j = 0; j < 4; j++) MMA_BF16(acc[i][j], ah[i], b[j][0], b[j][1]);
#pragma unroll
            for (int i = 0; i < 4; i++)
#pragma unroll
                for (int j = 0; j < 4; j++) MMA_BF16(acc[i][j], al[i], b[j][0], b[j][1]);
#pragma unroll
            for (int j = 0; j < 4; j++) {
                int row = wn * 32 + j * 8 + b_r;
                LDSM_X2(b[j][0], b[j][1],
                        smem_u32(&sBlo[row * SSTR + koff + b_c]));
            }
#pragma unroll
            for (int i = 0; i < 4; i++)
#pragma unroll
                for (int j = 0; j < 4; j++) MMA_BF16(acc[i][j], ah[i], b[j][0], b[j][1]);
        }
        __syncthreads();
    }

    const int er = lane >> 2;
    const int ec = (lane & 3) << 1;
#pragma unroll
    for (int i = 0; i < 4; i++) {
        int gm0 = m0 + wm * 64 + i * 16 + er;
#pragma unroll
        for (int j = 0; j < 4; j++) {
            int gc = n0 + wn * 32 + j * 8 + ec;
            if (gm0 < M)
                *(float2*)(C + (size_t)gm0 * DM + gc) =
                    make_float2(acc[i][j][0], acc[i][j][1]);
            if (gm0 + 8 < M)
                *(float2*)(C + (size_t)(gm0 + 8) * DM + gc) =
                    make_float2(acc[i][j][2], acc[i][j][3]);
        }
    }
}

// ---------------------------------------------------------------------------
// Output GEMM + residual + LayerNorm fused.
// Block tile 64x256 (full rows), 8 warps, warp j owns cols 32j..32j+31.
// After mainloop, accs parked in smem [64][256]; warp-per-row LN writes out.
// ---------------------------------------------------------------------------
#define FA_CHUNK (64 * SSTR)
#define FB_CHUNK (256 * SSTR)
#define FSTAGE (2 * FA_CHUNK + 2 * FB_CHUNK)  // 25600 elems
#define FUSED_SMEM (2 * FSTAGE * 2)           // 102400 B

__global__ void __launch_bounds__(256, 2)
gemm_ln_kernel(const __nv_bfloat16* __restrict__ Ahi,
               const __nv_bfloat16* __restrict__ Alo,
               const float* __restrict__ x,
               const float* __restrict__ gamma,
               const float* __restrict__ beta,
               float* __restrict__ out, int M) {
    extern __shared__ __nv_bfloat16 sm[];

    const int tid = threadIdx.x;
    const int wid = tid >> 5;
    const int lane = tid & 31;
    const int wn = wid;  // 0..7, 32-col stripe
    const __nv_bfloat16* Bhi = g_Bhi + (size_t)3 * DM * DM;
    const __nv_bfloat16* Blo = g_Blo + (size_t)3 * DM * DM;
    const int m0 = blockIdx.x * 64;

    const int l_r = tid >> 2;
    const int l_c8 = (tid & 3) << 3;

    auto preload = [&](int kc, int s) {
        __nv_bfloat16* base = sm + s * FSTAGE;
        uint32_t sAhi = smem_u32(base);
        uint32_t sAlo = smem_u32(base + FA_CHUNK);
        uint32_t sBhi = smem_u32(base + 2 * FA_CHUNK);
        uint32_t sBlo = smem_u32(base + 2 * FA_CHUNK + FB_CHUNK);
        const int k0 = kc * 32;
        {
            int r = l_r;
            int gm = m0 + r;
            uint32_t soff = (uint32_t)(r * SSTR + l_c8) * 2;
            uint32_t szA = (gm < M) ? 16u : 0u;
            size_t ga = (size_t)gm * DM + k0 + l_c8;
            cp_async16(sAhi + soff, Ahi + ga, szA);
            cp_async16(sAlo + soff, Alo + ga, szA);
        }
#pragma unroll
        for (int it = 0; it < 4; it++) {
            int r = it * 64 + l_r;
            uint32_t soff = (uint32_t)(r * SSTR + l_c8) * 2;
            size_t gb = (size_t)r * DM + k0 + l_c8;
            cp_async16(sBhi + soff, Bhi + gb, 16u);
            cp_async16(sBlo + soff, Blo + gb, 16u);
        }
        cp_commit();
    };

    float acc[4][4][4];
#pragma unroll
    for (int i = 0; i < 4; i++)
#pragma unroll
        for (int j = 0; j < 4; j++)
#pragma unroll
            for (int r = 0; r < 4; r++) acc[i][j][r] = 0.f;

    const int a_r = lane & 15;
    const int a_c = (lane >> 4) << 3;
    const int b_r = lane & 7;
    const int b_c = ((lane >> 3) & 1) << 3;

    preload(0, 0);

#pragma unroll 1
    for (int kc = 0; kc < 8; kc++) {
        if (kc < 7) {
            preload(kc + 1, (kc + 1) & 1);
            cp_wait<1>();
        } else {
            cp_wait<0>();
        }
        __syncthreads();

        __nv_bfloat16* base = sm + (kc & 1) * FSTAGE;
        __nv_bfloat16* sAhi = base;
        __nv_bfloat16* sAlo = base + FA_CHUNK;
        __nv_bfloat16* sBhi = base + 2 * FA_CHUNK;
        __nv_bfloat16* sBlo = base + 2 * FA_CHUNK + FB_CHUNK;

#pragma unroll
        for (int ks = 0; ks < 2; ks++) {
            const int koff = ks * 16;
            uint32_t ah[4][4], al[4][4];
#pragma unroll
            for (int i = 0; i < 4; i++) {
                int row = i * 16 + a_r;
                LDSM_X4(ah[i][0], ah[i][1], ah[i][2], ah[i][3],
                        smem_u32(&sAhi[row * SSTR + koff + a_c]));
                LDSM_X4(al[i][0], al[i][1], al[i][2], al[i][3],
                        smem_u32(&sAlo[row * SSTR + koff + a_c]));
            }
            uint32_t b[4][2];
#pragma unroll
            for (int j = 0; j < 4; j++) {
                int row = wn * 32 + j * 8 + b_r;
                LDSM_X2(b[j][0], b[j][1],
                        smem_u32(&sBhi[row * SSTR + koff + b_c]));
            }
#pragma unroll
            for (int i = 0; i < 4; i++)
#pragma unroll
                for (int j = 0; j < 4; j++) MMA_BF16(acc[i][j], ah[i], b[j][0], b[j][1]);
#pragma unroll
            for (int i = 0; i < 4; i++)
#pragma unroll
                for (int j = 0; j < 4; j++) MMA_BF16(acc[i][j], al[i], b[j][0], b[j][1]);
#pragma unroll
            for (int j = 0; j < 4; j++) {
                int row = wn * 32 + j * 8 + b_r;
                LDSM_X2(b[j][0], b[j][1],
                        smem_u32(&sBlo[row * SSTR + koff + b_c]));
            }
#pragma unroll
            for (int i = 0; i < 4; i++)
#pragma unroll
                for (int j = 0; j < 4; j++) MMA_BF16(acc[i][j], ah[i], b[j][0], b[j][1]);
        }
        __syncthreads();
    }

    // ---- park tile in smem: sOut[64][256] (65536 B, reuses pipeline smem) --
    float* sOut = (float*)sm;
    const int er = lane >> 2;
    const int ec = (lane & 3) << 1;
#pragma unroll
    for (int i = 0; i < 4; i++) {
        int r0 = i * 16 + er;
#pragma unroll
        for (int j = 0; j < 4; j++) {
            int c = wn * 32 + j * 8 + ec;
            sOut[r0 * 256 + c] = acc[i][j][0];
            sOut[r0 * 256 + c + 1] = acc[i][j][1];
            sOut[(r0 + 8) * 256 + c] = acc[i][j][2];
            sOut[(r0 + 8) * 256 + c + 1] = acc[i][j][3];
        }
    }
    __syncthreads();

    // ---- residual + LN: warp per row (8 rows per warp), lane owns 8 cols --
    const float4* g4 = (const float4*)gamma;
    const float4* b4 = (const float4*)beta;
    float4 ga = g4[2 * lane], gb = g4[2 * lane + 1];
    float4 ba = b4[2 * lane], bb = b4[2 * lane + 1];

#pragma unroll 1
    for (int rr = 0; rr < 8; rr++) {
        int r = wid * 8 + rr;
        int gm = m0 + r;
        if (gm >= M) break;
        const float4* x4 = (const float4*)(x + (size_t)gm * DM);
        float4 xa = x4[2 * lane], xb = x4[2 * lane + 1];
        const float* srow = sOut + r * 256 + 8 * lane;
        float v[8];
#pragma unroll
        for (int j = 0; j < 4; j++) v[j] = srow[j] + (&xa.x)[j];
#pragma unroll
        for (int j = 0; j < 4; j++) v[4 + j] = srow[4 + j] + (&xb.x)[j];

        float s = 0.f;
#pragma unroll
        for (int j = 0; j < 8; j++) s += v[j];
#pragma unroll
        for (int o = 16; o; o >>= 1) s += __shfl_xor_sync(0xFFFFFFFFu, s, o);
        float mu = s * (1.f / DM);

        float sq = 0.f;
#pragma unroll
        for (int j = 0; j < 8; j++) {
            float dv = v[j] - mu;
            sq += dv * dv;
        }
#pragma unroll
        for (int o = 16; o; o >>= 1) sq += __shfl_xor_sync(0xFFFFFFFFu, sq, o);
        float rstd = rsqrtf(sq * (1.f / DM) + 1e-5f);

        float4 r0, r1;
        r0.x = (v[0] - mu) * rstd * ga.x + ba.x;
        r0.y = (v[1] - mu) * rstd * ga.y + ba.y;
        r0.z = (v[2] - mu) * rstd * ga.z + ba.z;
        r0.w = (v[3] - mu) * rstd * ga.w + ba.w;
        r1.x = (v[4] - mu) * rstd * gb.x + bb.x;
        r1.y = (v[5] - mu) * rstd * gb.y + bb.y;
        r1.z = (v[6] - mu) * rstd * gb.z + bb.z;
        r1.w = (v[7] - mu) * rstd * gb.w + bb.w;

        float4* out4 = (float4*)(out + (size_t)gm * DM);
        out4[2 * lane] = r0;
        out4[2 * lane + 1] = r1;
    }
}

// ---------------------------------------------------------------------------
// Node aggregation: warp per node, Q in regs, stream neighbor K/V with
// next-index prefetch, softmax in registers, write hi/lo bf16 directly.
// ---------------------------------------------------------------------------
__global__ void node_agg_kernel() {
    int n = blockIdx.x * (blockDim.x >> 5) + (threadIdx.x >> 5);
    if (n >= NN) return;
    int lane = threadIdx.x & 31;

    const float4* q4 = (const float4*)(g_Q + (size_t)n * DM);
    float4 qa = q4[2 * lane], qb = q4[2 * lane + 1];

    int beg = g_off[n];
    int end = g_off[n + 1];

    float acc[8] = {0.f, 0.f, 0.f, 0.f, 0.f, 0.f, 0.f, 0.f};
    float den = 0.f;

    int d = (beg < end) ? __ldg(&g_edst[beg]) : 0;
#pragma unroll 1
    for (int i = beg; i < end; i++) {
        int dn = (i + 1 < end) ? __ldg(&g_edst[i + 1]) : 0;
        const float4* k4 = (const float4*)(g_K + (size_t)d * DM);
        const float4* v4 = (const float4*)(g_V + (size_t)d * DM);
        float4 ka = k4[2 * lane], kb = k4[2 * lane + 1];
        float4 va = v4[2 * lane], vb = v4[2 * lane + 1];

        float p = qa.x * ka.x + qa.y * ka.y + qa.z * ka.z + qa.w * ka.w +
                  qb.x * kb.x + qb.y * kb.y + qb.z * kb.z + qb.w * kb.w;
        p += __shfl_xor_sync(0xFFFFFFFFu, p, 1);
        p += __shfl_xor_sync(0xFFFFFFFFu, p, 2);

        float ex = __expf(p * SCALE);
        den += ex;
        acc[0] += ex * va.x; acc[1] += ex * va.y;
        acc[2] += ex * va.z; acc[3] += ex * va.w;
        acc[4] += ex * vb.x; acc[5] += ex * vb.y;
        acc[6] += ex * vb.z; acc[7] += ex * vb.w;
        d = dn;
    }

    float inv = (den > 0.f) ? 1.f / den : 0.f;
    __nv_bfloat16 hi8[8], lo8[8];
#pragma unroll
    for (int j = 0; j < 8; j++) {
        float v = acc[j] * inv;
        __nv_bfloat16 hi = __float2bfloat16(v);
        hi8[j] = hi;
        lo8[j] = __float2bfloat16(v - __bfloat162float(hi));
    }
    size_t base = (size_t)n * DM + 8 * lane;
    *(uint4*)(g_Ahi + base) = *(const uint4*)hi8;
    *(uint4*)(g_Alo + base) = *(const uint4*)lo8;
}

// ---------------------------------------------------------------------------
extern "C" void kernel_launch(void* const* d_in, const int* in_sizes, int n_in,
                              void* d_out, int out_size) {
    const float* x     = (const float*)d_in[0];
    const int*   eidx  = (const int*)d_in[1];
    const float* Wq    = (const float*)d_in[2];
    const float* Wk    = (const float*)d_in[3];
    const float* Wv    = (const float*)d_in[4];
    const float* Wo    = (const float*)d_in[5];
    const float* gamma = (const float*)d_in[6];
    const float* beta  = (const float*)d_in[7];
    float* out = (float*)d_out;

    const int* src = eidx;
    const int* dst = eidx + NE;

    float* Qp = nullptr; cudaGetSymbolAddress((void**)&Qp, g_Q);
    float* Kp = nullptr; cudaGetSymbolAddress((void**)&Kp, g_K);
    float* Vp = nullptr; cudaGetSymbolAddress((void**)&Vp, g_V);
    __nv_bfloat16* Ahip = nullptr; cudaGetSymbolAddress((void**)&Ahip, g_Ahi);
    __nv_bfloat16* Alop = nullptr; cudaGetSymbolAddress((void**)&Alop, g_Alo);

    cudaFuncSetAttribute(mma_gemm_kernel,
                         cudaFuncAttributeMaxDynamicSharedMemorySize, GEMM_SMEM);
    cudaFuncSetAttribute(gemm_ln_kernel,
                         cudaFuncAttributeMaxDynamicSharedMemorySize, FUSED_SMEM);

    // side stream + fork/join events (handles created once; no device mem)
    static cudaStream_t s2 = nullptr;
    static cudaEvent_t eA = nullptr, eB = nullptr;
    if (s2 == nullptr) {
        cudaStreamCreateWithFlags(&s2, cudaStreamNonBlocking);
        cudaEventCreateWithFlags(&eA, cudaEventDisableTiming);
        cudaEventCreateWithFlags(&eB, cudaEventDisableTiming);
    }

    // merged prep: x hi/lo, W hi/lo transposed, zero cnt
    prep_all_kernel<<<(PREP_TOTAL + 255) / 256, 256>>>(x, Wq, Wk, Wv, Wo);
    cudaEventRecord(eA, 0);

    // QKV tensor-core GEMMs on main stream (z selects matrix)
    dim3 gq((NN + 127) / 128, DM / 128, 3);
    mma_gemm_kernel<<<gq, 256, GEMM_SMEM>>>(Ahip, Alop, Qp, Kp, Vp, NN);

    // CSR build on side stream, concurrent with QKV GEMM
    cudaStreamWaitEvent(s2, eA, 0);
    hist_kernel<<<(NE + 255) / 256, 256, 0, s2>>>(src);
    scan_kernel<<<1, 1024, 0, s2>>>();
    scatter_kernel<<<(NE + 255) / 256, 256, 0, s2>>>(src, dst);
    cudaEventRecord(eB, s2);

    // join: aggregation needs both QKV (main) and CSR (side)
    cudaStreamWaitEvent(0, eB, 0);
    node_agg_kernel<<<(NN + 7) / 8, 256>>>();

    // fused output GEMM + residual + LayerNorm -> d_out
    gemm_ln_kernel<<<(NN + 63) / 64, 256, FUSED_SMEM>>>(Ahip, Alop, x, gamma,
                                                        beta, out, NN);
}